// round 2
// baseline (speedup 1.0000x reference)
#include <cuda_runtime.h>
#include <cstdint>

#define BATCH 4
#define HH 256
#define WW 256
#define NCC 64
#define NHID 18
#define EPSV 1e-5f

// ---------------- device scratch (allocation-free rule: __device__ globals) ----------------
__device__ float g_buf0[BATCH * HH * WW * NCC];   // 64 MB NHWC activations (ping)
__device__ float g_buf1[BATCH * HH * WW * NCC];   // 64 MB NHWC activations (pong)
__device__ __align__(16) float g_wh[NCC * 9 * NCC];   // folded hidden weights [ci][tap][co]
__device__ float g_bh[NCC];
__device__ __align__(16) float g_win[3 * 9 * NCC];    // folded input weights [ci][tap][co]
__device__ float g_bin[NCC];
__device__ __align__(16) float g_wout[NCC * 9 * 3];   // folded output weights [ci][tap][co]
__device__ float g_bout[3];

// ---------------- helpers ----------------
__device__ __forceinline__ float selu_f(float x) {
    const float sc = 1.0507009873554805f;
    const float scal = 1.7580993408473766f; // scale * alpha
    return x > 0.f ? sc * x : scal * (expf(x) - 1.f);
}

__device__ __forceinline__ unsigned long long pack2(float v) {
    unsigned long long r;
    asm("mov.b64 %0, {%1, %1};" : "=l"(r) : "f"(v));
    return r;
}
__device__ __forceinline__ unsigned long long packpair(float lo, float hi) {
    unsigned long long r;
    asm("mov.b64 %0, {%1, %2};" : "=l"(r) : "f"(lo), "f"(hi));
    return r;
}
__device__ __forceinline__ void unpack2(unsigned long long v, float& lo, float& hi) {
    asm("mov.b64 {%0, %1}, %2;" : "=f"(lo), "=f"(hi) : "l"(v));
}
__device__ __forceinline__ void ffma2(unsigned long long& d, unsigned long long a, unsigned long long b) {
    asm("fma.rn.f32x2 %0, %1, %2, %0;" : "+l"(d) : "l"(a), "l"(b));
}

// ---------------- prep: fold BN into weights/biases ----------------
__global__ void prep_kernel(
    const float* __restrict__ w_in, const float* __restrict__ b_in,
    const float* __restrict__ g_in, const float* __restrict__ be_in,
    const float* __restrict__ m_in, const float* __restrict__ v_in,
    const float* __restrict__ w_h,  const float* __restrict__ b_h,
    const float* __restrict__ g_h,  const float* __restrict__ be_h,
    const float* __restrict__ m_h,  const float* __restrict__ v_h,
    const float* __restrict__ w_out, const float* __restrict__ b_out,
    const float* __restrict__ g_out, const float* __restrict__ be_out,
    const float* __restrict__ m_out, const float* __restrict__ v_out)
{
    int idx = blockIdx.x * blockDim.x + threadIdx.x;
    if (idx < NCC * 9 * NCC) {   // hidden weights: target [(ci*9+tap)*64+co]
        int co = idx & 63;
        int rest = idx >> 6;
        int tap = rest % 9;
        int ci = rest / 9;
        float s = g_h[co] * rsqrtf(v_h[co] + EPSV);
        g_wh[idx] = w_h[(co * NCC + ci) * 9 + tap] * s;
    }
    if (idx < 3 * 9 * NCC) {     // input weights: target [(ci*9+tap)*64+co], ci<3
        int co = idx & 63;
        int rest = idx >> 6;
        int tap = rest % 9;
        int ci = rest / 9;
        float s = g_in[co] * rsqrtf(v_in[co] + EPSV);
        g_win[idx] = w_in[(co * 3 + ci) * 9 + tap] * s;
    }
    if (idx < NCC * 9 * 3) {     // output weights: target [(ci*9+tap)*3+co], co<3
        int co = idx % 3;
        int rest = idx / 3;
        int tap = rest % 9;
        int ci = rest / 9;
        float s = g_out[co] * rsqrtf(v_out[co] + EPSV);
        g_wout[idx] = w_out[(co * NCC + ci) * 9 + tap] * s;
    }
    if (idx < NCC) {
        g_bh[idx]  = (b_h[idx]  - m_h[idx])  * (g_h[idx]  * rsqrtf(v_h[idx]  + EPSV)) + be_h[idx];
        g_bin[idx] = (b_in[idx] - m_in[idx]) * (g_in[idx] * rsqrtf(v_in[idx] + EPSV)) + be_in[idx];
    }
    if (idx < 3) {
        g_bout[idx] = (b_out[idx] - m_out[idx]) * (g_out[idx] * rsqrtf(v_out[idx] + EPSV)) + be_out[idx];
    }
}

// ---------------- input conv 3->64 + BN + SELU, NCHW -> NHWC ----------------
__global__ __launch_bounds__(128) void in_conv_kernel(const float* __restrict__ X, float* __restrict__ out)
{
    __shared__ __align__(16) float s_w[3 * 9 * NCC];
    __shared__ __align__(16) float s_b[NCC];
    int tid = threadIdx.x;
    for (int i = tid; i < 3 * 9 * NCC; i += 128) s_w[i] = g_win[i];
    if (tid < NCC) s_b[tid] = g_bin[tid];
    __syncthreads();

    int p = blockIdx.x * 128 + tid;              // 0 .. B*H*W-1
    int b = p >> 16;
    int y = (p >> 8) & 255;
    int x = p & 255;
    const float* Xb = X + (size_t)b * 3 * HH * WW;

    float4 acc[16];
    #pragma unroll
    for (int q = 0; q < 16; q++) acc[q] = ((const float4*)s_b)[q];

    #pragma unroll
    for (int ci = 0; ci < 3; ci++) {
        #pragma unroll
        for (int dy = 0; dy < 3; dy++) {
            int gy = y + dy - 1;
            #pragma unroll
            for (int dx = 0; dx < 3; dx++) {
                int gx = x + dx - 1;
                float v = 0.f;
                if (gy >= 0 && gy < HH && gx >= 0 && gx < WW)
                    v = Xb[ci * HH * WW + gy * WW + gx];
                const float4* w4 = (const float4*)(s_w + (ci * 9 + dy * 3 + dx) * NCC);
                #pragma unroll
                for (int q = 0; q < 16; q++) {
                    float4 w = w4[q];
                    acc[q].x += v * w.x; acc[q].y += v * w.y;
                    acc[q].z += v * w.z; acc[q].w += v * w.w;
                }
            }
        }
    }
    float4* op = (float4*)(out + (size_t)p * NCC);
    #pragma unroll
    for (int q = 0; q < 16; q++) {
        float4 a = acc[q];
        a.x = selu_f(a.x); a.y = selu_f(a.y); a.z = selu_f(a.z); a.w = selu_f(a.w);
        op[q] = a;
    }
}

// ---------------- hidden conv 64->64 + BN + SELU (f32x2 packed FMA) ----------------
#define TILE 16
#define CK 8
#define HALO 18
#define AP 19

__global__ __launch_bounds__(256, 2) void hidden_kernel(const float* __restrict__ in, float* __restrict__ out)
{
    __shared__ __align__(16) float s_w[CK * 9 * NCC];        // [ciL][tap][co]
    __shared__ __align__(16) float s_act[CK][HALO * AP];     // [ciL][y*AP+x]

    int tid = threadIdx.x;
    int cg = tid & 7;            // channel group -> co0 = cg*8
    int pg = tid >> 3;           // pixel group (0..31)
    int co0 = cg * 8;
    int r = pg >> 1;             // tile row 0..15
    int cs = (pg & 1) * 8;       // tile col start 0 or 8
    int tx0 = blockIdx.x * TILE;
    int ty0 = blockIdx.y * TILE;
    int b = blockIdx.z;
    const float* inB = in + (size_t)b * HH * WW * NCC;
    float* outB = out + (size_t)b * HH * WW * NCC;

    unsigned long long acc[8][4];
    {
        float bias[8];
        #pragma unroll
        for (int k = 0; k < 8; k++) bias[k] = g_bh[co0 + k];
        #pragma unroll
        for (int j = 0; j < 8; j++)
            #pragma unroll
            for (int k2 = 0; k2 < 4; k2++)
                acc[j][k2] = packpair(bias[2 * k2], bias[2 * k2 + 1]);
    }

    for (int c = 0; c < NCC / CK; c++) {
        __syncthreads();
        // load weight chunk (contiguous)
        {
            const float4* wsrc = (const float4*)(g_wh + c * CK * 9 * NCC);
            float4* wdst = (float4*)s_w;
            #pragma unroll
            for (int i = tid; i < CK * 9 * NCC / 4; i += 256) wdst[i] = wsrc[i];
        }
        // load activation halo chunk (float4 along channel)
        for (int i = tid; i < HALO * HALO * (CK / 4); i += 256) {
            int ci4 = i & (CK / 4 - 1);
            int p = i / (CK / 4);
            int y = p / HALO, x = p % HALO;
            int gy = ty0 + y - 1, gx = tx0 + x - 1;
            float4 v = make_float4(0.f, 0.f, 0.f, 0.f);
            if (gy >= 0 && gy < HH && gx >= 0 && gx < WW)
                v = *(const float4*)(inB + ((size_t)(gy * WW + gx)) * NCC + c * CK + ci4 * 4);
            int base = y * AP + x;
            s_act[ci4 * 4 + 0][base] = v.x;
            s_act[ci4 * 4 + 1][base] = v.y;
            s_act[ci4 * 4 + 2][base] = v.z;
            s_act[ci4 * 4 + 3][base] = v.w;
        }
        __syncthreads();

        #pragma unroll 2
        for (int ci = 0; ci < CK; ci++) {
            #pragma unroll
            for (int dy = 0; dy < 3; dy++) {
                unsigned long long avv[10];
                #pragma unroll
                for (int t = 0; t < 10; t++)
                    avv[t] = pack2(s_act[ci][(r + dy) * AP + cs + t]);
                #pragma unroll
                for (int dx = 0; dx < 3; dx++) {
                    const ulonglong2* wp = (const ulonglong2*)(s_w + (ci * 9 + dy * 3 + dx) * NCC + co0);
                    ulonglong2 wa = wp[0], wb = wp[1];
                    unsigned long long wv0 = wa.x, wv1 = wa.y, wv2 = wb.x, wv3 = wb.y;
                    #pragma unroll
                    for (int j = 0; j < 8; j++) {
                        unsigned long long a = avv[dx + j];
                        ffma2(acc[j][0], a, wv0);
                        ffma2(acc[j][1], a, wv1);
                        ffma2(acc[j][2], a, wv2);
                        ffma2(acc[j][3], a, wv3);
                    }
                }
            }
        }
    }

    // epilogue: SELU + store NHWC
    int gy = ty0 + r;
    #pragma unroll
    for (int j = 0; j < 8; j++) {
        int gx = tx0 + cs + j;
        float v[8];
        #pragma unroll
        for (int k2 = 0; k2 < 4; k2++) unpack2(acc[j][k2], v[2 * k2], v[2 * k2 + 1]);
        #pragma unroll
        for (int k = 0; k < 8; k++) v[k] = selu_f(v[k]);
        float4* op = (float4*)(outB + ((size_t)(gy * WW + gx)) * NCC + co0);
        op[0] = make_float4(v[0], v[1], v[2], v[3]);
        op[1] = make_float4(v[4], v[5], v[6], v[7]);
    }
}

// ---------------- output conv 64->3 + BN + SELU + bayer-interp residual ----------------
__global__ __launch_bounds__(128) void out_conv_kernel(const float* __restrict__ A,
                                                       const float* __restrict__ X,
                                                       float* __restrict__ out)
{
    __shared__ float s_w[NCC * 9 * 3];
    __shared__ float s_b[4];
    int tid = threadIdx.x;
    for (int i = tid; i < NCC * 9 * 3; i += 128) s_w[i] = g_wout[i];
    if (tid < 3) s_b[tid] = g_bout[tid];
    __syncthreads();

    int p = blockIdx.x * 128 + tid;
    int b = p >> 16;
    int y = (p >> 8) & 255;
    int x = p & 255;

    float acc0 = s_b[0], acc1 = s_b[1], acc2 = s_b[2];
    #pragma unroll
    for (int dy = 0; dy < 3; dy++) {
        int gy = y + dy - 1;
        #pragma unroll
        for (int dx = 0; dx < 3; dx++) {
            int gx = x + dx - 1;
            if (gy < 0 || gy >= HH || gx < 0 || gx >= WW) continue;
            int tap = dy * 3 + dx;
            const float4* ap = (const float4*)(A + ((size_t)b * HH * WW + (size_t)gy * WW + gx) * NCC);
            #pragma unroll
            for (int q = 0; q < 16; q++) {
                float4 v = ap[q];
                int ci = q * 4;
                const float* w = s_w + (ci * 9 + tap) * 3;
                acc0 += v.x * w[0]; acc1 += v.x * w[1]; acc2 += v.x * w[2];
                w = s_w + ((ci + 1) * 9 + tap) * 3;
                acc0 += v.y * w[0]; acc1 += v.y * w[1]; acc2 += v.y * w[2];
                w = s_w + ((ci + 2) * 9 + tap) * 3;
                acc0 += v.z * w[0]; acc1 += v.z * w[1]; acc2 += v.z * w[2];
                w = s_w + ((ci + 3) * 9 + tap) * 3;
                acc0 += v.w * w[0]; acc1 += v.w * w[1]; acc2 += v.w * w[2];
            }
        }
    }
    float sel[3] = { selu_f(acc0), selu_f(acc1), selu_f(acc2) };

    // bayer zero interpolation residual on X (NCHW)
    #pragma unroll
    for (int c = 0; c < 3; c++) {
        const float* Xc = X + ((size_t)b * 3 + c) * HH * WW;
        float xv = Xc[y * WW + x];
        float l = (x > 0)      ? Xc[y * WW + x - 1] : 0.f;
        float rr = (x < WW - 1) ? Xc[y * WW + x + 1] : 0.f;
        float t = (y > 0)      ? Xc[(y - 1) * WW + x] : 0.f;
        float bt = (y < HH - 1) ? Xc[(y + 1) * WW + x] : 0.f;
        float nb_sum = l + rr + t + bt;
        float nb_cnt = (l > 0.f) + (rr > 0.f) + (t > 0.f) + (bt > 0.f);
        float mean = nb_cnt > 0.f ? nb_sum / nb_cnt : 0.f;
        float res = (xv == 0.f) ? mean : xv;
        out[((size_t)b * 3 + c) * HH * WW + (size_t)y * WW + x] = sel[c] + res;
    }
}

// ---------------- launch ----------------
extern "C" void kernel_launch(void* const* d_in, const int* in_sizes, int n_in,
                              void* d_out, int out_size)
{
    const float* X     = (const float*)d_in[0];
    const float* w_in  = (const float*)d_in[1];
    const float* b_in  = (const float*)d_in[2];
    const float* gi    = (const float*)d_in[3];
    const float* bei   = (const float*)d_in[4];
    const float* mi    = (const float*)d_in[5];
    const float* vi    = (const float*)d_in[6];
    const float* w_h   = (const float*)d_in[7];
    const float* b_h   = (const float*)d_in[8];
    const float* gh    = (const float*)d_in[9];
    const float* beh   = (const float*)d_in[10];
    const float* mh    = (const float*)d_in[11];
    const float* vh    = (const float*)d_in[12];
    const float* w_out = (const float*)d_in[13];
    const float* b_out = (const float*)d_in[14];
    const float* go    = (const float*)d_in[15];
    const float* beo   = (const float*)d_in[16];
    const float* mo    = (const float*)d_in[17];
    const float* vo    = (const float*)d_in[18];
    float* out = (float*)d_out;

    float *buf0, *buf1;
    cudaGetSymbolAddress((void**)&buf0, g_buf0);
    cudaGetSymbolAddress((void**)&buf1, g_buf1);

    prep_kernel<<<(NCC * 9 * NCC + 255) / 256, 256>>>(
        w_in, b_in, gi, bei, mi, vi,
        w_h, b_h, gh, beh, mh, vh,
        w_out, b_out, go, beo, mo, vo);

    const int NPIX = BATCH * HH * WW;
    in_conv_kernel<<<NPIX / 128, 128>>>(X, buf0);

    dim3 hgrid(WW / TILE, HH / TILE, BATCH);
    for (int l = 0; l < NHID; l++) {
        const float* src = (l & 1) ? buf1 : buf0;
        float* dst = (l & 1) ? buf0 : buf1;
        hidden_kernel<<<hgrid, 256>>>(src, dst);
    }
    // NHID=18 (even) -> final activations in buf0
    out_conv_kernel<<<NPIX / 128, 128>>>(buf0, X, out);
}

// round 8
// speedup vs baseline: 1.7703x; 1.7703x over previous
#include <cuda_runtime.h>
#include <cuda_fp16.h>
#include <cstdint>

#define BATCH 4
#define HH 256
#define WW 256
#define NCC 64
#define NHID 18
#define EPSV 1e-5f

typedef __half fp16;

// ---------------- device scratch ----------------
__device__ __align__(16) fp16 g_h0[BATCH * HH * WW * NCC];
__device__ __align__(16) fp16 g_l0[BATCH * HH * WW * NCC];
__device__ __align__(16) fp16 g_h1[BATCH * HH * WW * NCC];
__device__ __align__(16) fp16 g_l1[BATCH * HH * WW * NCC];
__device__ __align__(16) fp16 g_whx[9 * 2 * NCC * NCC];   // [tap][term][ci][co]
__device__ float g_bh[NCC];
__device__ __align__(16) float g_win[3 * 9 * NCC];
__device__ float g_bin[NCC];
__device__ __align__(16) float g_wout[NCC * 9 * 3];
__device__ float g_bout[3];

// ---------------- helpers ----------------
__device__ __forceinline__ float selu_f(float x) {
    const float sc = 1.0507009873554805f;
    const float scal = 1.7580993408473766f;
    return x > 0.f ? sc * x : scal * (expf(x) - 1.f);
}
__device__ __forceinline__ uint32_t smem_u32(const void* p) {
    uint32_t a;
    asm("{ .reg .u64 t; cvta.to.shared.u64 t, %1; cvt.u32.u64 %0, t; }" : "=r"(a) : "l"(p));
    return a;
}
__device__ __forceinline__ void cpa16(uint32_t dst, const void* src, bool pred) {
    int sz = pred ? 16 : 0;
    asm volatile("cp.async.cg.shared.global [%0], [%1], 16, %2;" :: "r"(dst), "l"(src), "r"(sz) : "memory");
}
#define CP_COMMIT() asm volatile("cp.async.commit_group;" ::: "memory")
#define CP_WAIT0()  asm volatile("cp.async.wait_group 0;" ::: "memory")

__device__ __forceinline__ void ldsm_x4(uint32_t (&r)[4], uint32_t addr) {
    asm volatile("ldmatrix.sync.aligned.m8n8.x4.shared.b16 {%0,%1,%2,%3}, [%4];"
                 : "=r"(r[0]), "=r"(r[1]), "=r"(r[2]), "=r"(r[3]) : "r"(addr));
}
__device__ __forceinline__ void ldsm_x2t(uint32_t (&r)[2], uint32_t addr) {
    asm volatile("ldmatrix.sync.aligned.m8n8.x2.trans.shared.b16 {%0,%1}, [%2];"
                 : "=r"(r[0]), "=r"(r[1]) : "r"(addr));
}
__device__ __forceinline__ void mma16816(float (&d)[4], const uint32_t (&a)[4], const uint32_t (&bb)[2]) {
    asm volatile("mma.sync.aligned.m16n8k16.row.col.f32.f16.f16.f32 "
                 "{%0,%1,%2,%3}, {%4,%5,%6,%7}, {%8,%9}, {%0,%1,%2,%3};"
                 : "+f"(d[0]), "+f"(d[1]), "+f"(d[2]), "+f"(d[3])
                 : "r"(a[0]), "r"(a[1]), "r"(a[2]), "r"(a[3]), "r"(bb[0]), "r"(bb[1]));
}

// smem layout for hidden kernel
static constexpr int A_TILE = 132 * 128;                  // bytes per (term,dy) tile
static constexpr int SMEM_A = 1024;                       // bias at 0
static constexpr int SMEM_WB = SMEM_A + 6 * A_TILE;       // 1024 + 101376 = 102400
static constexpr int WSTAGE = 2 * NCC * NCC * 2;          // 16384 bytes per tap
static constexpr int SMEM_TOT = SMEM_WB + 2 * WSTAGE;     // 135168

// ---------------- prep: fold BN, split weights to fp16 hi/lo ----------------
__global__ void prep_kernel(
    const float* __restrict__ w_in, const float* __restrict__ b_in,
    const float* __restrict__ g_in, const float* __restrict__ be_in,
    const float* __restrict__ m_in, const float* __restrict__ v_in,
    const float* __restrict__ w_h,  const float* __restrict__ b_h,
    const float* __restrict__ g_h,  const float* __restrict__ be_h,
    const float* __restrict__ m_h,  const float* __restrict__ v_h,
    const float* __restrict__ w_out, const float* __restrict__ b_out,
    const float* __restrict__ g_out, const float* __restrict__ be_out,
    const float* __restrict__ m_out, const float* __restrict__ v_out)
{
    int idx = blockIdx.x * blockDim.x + threadIdx.x;
    if (idx < 9 * 2 * NCC * NCC) {        // [tap][term][ci][co]
        int co = idx & 63;
        int ci = (idx >> 6) & 63;
        int term = (idx >> 12) & 1;
        int tap = idx >> 13;
        float s = g_h[co] * rsqrtf(v_h[co] + EPSV);
        float wf = w_h[(co * NCC + ci) * 9 + tap] * s;
        fp16 hi = __float2half_rn(wf);
        g_whx[idx] = (term == 0) ? hi : __float2half_rn(wf - __half2float(hi));
    }
    if (idx < 3 * 9 * NCC) {
        int co = idx & 63;
        int rest = idx >> 6;
        int tap = rest % 9;
        int ci = rest / 9;
        float s = g_in[co] * rsqrtf(v_in[co] + EPSV);
        g_win[idx] = w_in[(co * 3 + ci) * 9 + tap] * s;
    }
    if (idx < NCC * 9 * 3) {
        int co = idx % 3;
        int rest = idx / 3;
        int tap = rest % 9;
        int ci = rest / 9;
        float s = g_out[co] * rsqrtf(v_out[co] + EPSV);
        g_wout[idx] = w_out[(co * NCC + ci) * 9 + tap] * s;
    }
    if (idx < NCC) {
        g_bh[idx]  = (b_h[idx]  - m_h[idx])  * (g_h[idx]  * rsqrtf(v_h[idx]  + EPSV)) + be_h[idx];
        g_bin[idx] = (b_in[idx] - m_in[idx]) * (g_in[idx] * rsqrtf(v_in[idx] + EPSV)) + be_in[idx];
    }
    if (idx < 3) {
        g_bout[idx] = (b_out[idx] - m_out[idx]) * (g_out[idx] * rsqrtf(v_out[idx] + EPSV)) + be_out[idx];
    }
}

// ---------------- input conv 3->64 + BN + SELU, NCHW -> NHWC fp16 hi/lo ----------------
__global__ __launch_bounds__(128) void in_conv_kernel(const float* __restrict__ X,
                                                      fp16* __restrict__ oh, fp16* __restrict__ ol)
{
    __shared__ __align__(16) float s_w[3 * 9 * NCC];
    __shared__ __align__(16) float s_b[NCC];
    int tid = threadIdx.x;
    for (int i = tid; i < 3 * 9 * NCC; i += 128) s_w[i] = g_win[i];
    if (tid < NCC) s_b[tid] = g_bin[tid];
    __syncthreads();

    int p = blockIdx.x * 128 + tid;
    int b = p >> 16;
    int y = (p >> 8) & 255;
    int x = p & 255;
    const float* Xb = X + (size_t)b * 3 * HH * WW;

    float4 acc[16];
    #pragma unroll
    for (int q = 0; q < 16; q++) acc[q] = ((const float4*)s_b)[q];

    #pragma unroll
    for (int ci = 0; ci < 3; ci++) {
        #pragma unroll
        for (int dy = 0; dy < 3; dy++) {
            int gy = y + dy - 1;
            #pragma unroll
            for (int dx = 0; dx < 3; dx++) {
                int gx = x + dx - 1;
                float v = 0.f;
                if (gy >= 0 && gy < HH && gx >= 0 && gx < WW)
                    v = Xb[ci * HH * WW + gy * WW + gx];
                const float4* w4 = (const float4*)(s_w + (ci * 9 + dy * 3 + dx) * NCC);
                #pragma unroll
                for (int q = 0; q < 16; q++) {
                    float4 w = w4[q];
                    acc[q].x += v * w.x; acc[q].y += v * w.y;
                    acc[q].z += v * w.z; acc[q].w += v * w.w;
                }
            }
        }
    }
    fp16 hv[64], lv[64];
    #pragma unroll
    for (int q = 0; q < 16; q++) {
        float vv[4] = { acc[q].x, acc[q].y, acc[q].z, acc[q].w };
        #pragma unroll
        for (int j = 0; j < 4; j++) {
            float v = selu_f(vv[j]);
            fp16 h = __float2half_rn(v);
            hv[q * 4 + j] = h;
            lv[q * 4 + j] = __float2half_rn(v - __half2float(h));
        }
    }
    #pragma unroll
    for (int t = 0; t < 8; t++) {
        *(uint4*)(oh + (size_t)p * NCC + t * 8) = *(uint4*)(hv + t * 8);
        *(uint4*)(ol + (size_t)p * NCC + t * 8) = *(uint4*)(lv + t * 8);
    }
}

// ---------------- hidden conv 64->64 via mma.sync HMMA (3-term fp16 split) ----------------
// CTA: 256 thr = 8 warps; strip of 128 output px in one row; all 64 co.
// smem A: [term(2)][dy(3)] x 130 px x 64 ci fp16, 16B-group swizzle.
// W streamed per tap: [term][ci][co] fp16, double buffered.
__global__ __launch_bounds__(256, 1) void hidden_mma(const fp16* __restrict__ ah, const fp16* __restrict__ al,
                                                     fp16* __restrict__ oh, fp16* __restrict__ ol)
{
    extern __shared__ char smem[];
    float* s_bias = (float*)smem;
    uint32_t sAu = smem_u32(smem + SMEM_A);
    uint32_t sWu = smem_u32(smem + SMEM_WB);
    int tid = threadIdx.x;
    int x0 = blockIdx.x * 128;
    int y  = blockIdx.y;
    int b  = blockIdx.z;

    if (tid < 64) s_bias[tid] = g_bh[tid];

    // --- A halo tile loads: 6 tiles x 130 px x 8 groups of 16B ---
    for (int j = tid; j < 6 * 130 * 8; j += 256) {
        int g = j & 7;
        int p = (j >> 3) % 130;
        int t3 = (j >> 3) / 130;            // term*3 + dy
        int dy = t3 % 3;
        int gx = x0 - 1 + p, gy = y + dy - 1;
        bool v = (gx >= 0 && gx < WW && gy >= 0 && gy < HH);
        int gxc = v ? gx : 0;
        int gyc = (gy >= 0 && gy < HH) ? gy : 0;
        const fp16* base = (t3 >= 3) ? al : ah;
        const fp16* src = base + ((size_t)((b * HH + gyc) * WW) + gxc) * NCC + g * 8;
        uint32_t dst = sAu + t3 * A_TILE + p * 128 + ((g ^ (p & 7)) << 4);
        cpa16(dst, src, v);
    }
    // --- stage W tap 0 into buf 0 ---
    {
        const char* src = (const char*)g_whx;
        for (int j = tid; j < 1024; j += 256) {
            int g = j & 7, ci = (j >> 3) & 63, term = j >> 9;
            uint32_t dst = sWu + term * 8192 + ci * 128 + ((g ^ (ci & 7)) << 4);
            cpa16(dst, src + term * 8192 + ci * 128 + g * 16, true);
        }
    }
    CP_COMMIT();

    float acc[8][4];
    #pragma unroll
    for (int n0 = 0; n0 < 8; n0++)
        #pragma unroll
        for (int k = 0; k < 4; k++) acc[n0][k] = 0.f;

    int lane = tid & 31;
    int mp = (tid >> 5) << 4;       // warp's 16-px base
    int mat = lane >> 3, rr = lane & 7;
    int mrow = ((mat & 1) << 3) + rr;   // A m_local
    int kh = mat >> 1;                  // A k-half
    int l16 = lane & 15;                // B ci row within 16

    int wbuf = 0;
    for (int tap = 0; tap < 9; ++tap) {
        CP_WAIT0();
        __syncthreads();
        if (tap < 8) {
            const char* src = (const char*)g_whx + (tap + 1) * WSTAGE;
            uint32_t dstb = sWu + (wbuf ^ 1) * WSTAGE;
            for (int j = tid; j < 1024; j += 256) {
                int g = j & 7, ci = (j >> 3) & 63, term = j >> 9;
                uint32_t dst = dstb + term * 8192 + ci * 128 + ((g ^ (ci & 7)) << 4);
                cpa16(dst, src + term * 8192 + ci * 128 + g * 16, true);
            }
            CP_COMMIT();
        }
        int dy = tap / 3, dx = tap % 3;

        #pragma unroll
        for (int kc = 0; kc < 4; ++kc) {
            uint32_t a_hi[4], a_lo[4];
            {
                int s = mp + mrow + dx;       // strip px 0..129
                int g = kc * 2 + kh;
                uint32_t arow = (uint32_t)(dy * A_TILE + s * 128 + ((g ^ (s & 7)) << 4));
                ldsm_x4(a_hi, sAu + arow);
                ldsm_x4(a_lo, sAu + 3 * A_TILE + arow);
            }
            int ci = kc * 16 + l16;
            uint32_t wrow = sWu + wbuf * WSTAGE + ci * 128;
            uint32_t sw = (ci & 7) << 4;
            #pragma unroll
            for (int n0 = 0; n0 < 8; ++n0) {     // W hi: A_hi + A_lo terms
                uint32_t bf[2];
                ldsm_x2t(bf, wrow + ((n0 << 4) ^ sw));
                mma16816(acc[n0], a_hi, bf);
                mma16816(acc[n0], a_lo, bf);
            }
            #pragma unroll
            for (int n0 = 0; n0 < 8; ++n0) {     // W lo: A_hi term
                uint32_t bf[2];
                ldsm_x2t(bf, wrow + 8192 + ((n0 << 4) ^ sw));
                mma16816(acc[n0], a_hi, bf);
            }
        }
        __syncthreads();
        wbuf ^= 1;
    }

    // --- epilogue: bias + SELU + fp16 hi/lo split, store NHWC ---
    int q = lane >> 2;
    int cp2 = (lane & 3) << 1;
    #pragma unroll
    for (int n0 = 0; n0 < 8; ++n0) {
        float b0 = s_bias[n0 * 8 + cp2];
        float b1 = s_bias[n0 * 8 + cp2 + 1];
        #pragma unroll
        for (int hr = 0; hr < 2; ++hr) {
            int px = mp + q + hr * 8;
            float v0 = acc[n0][hr * 2 + 0] + b0;
            float v1 = acc[n0][hr * 2 + 1] + b1;
            v0 = selu_f(v0);
            v1 = selu_f(v1);
            fp16 h0 = __float2half_rn(v0);
            fp16 h1 = __float2half_rn(v1);
            fp16 lo0 = __float2half_rn(v0 - __half2float(h0));
            fp16 lo1 = __float2half_rn(v1 - __half2float(h1));
            size_t off = ((size_t)((b * HH + y) * WW) + (x0 + px)) * NCC + n0 * 8 + cp2;
            *(__half2*)(oh + off) = __halves2half2(h0, h1);
            *(__half2*)(ol + off) = __halves2half2(lo0, lo1);
        }
    }
}

// ---------------- output conv 64->3 + BN + SELU + bayer residual ----------------
__global__ __launch_bounds__(128) void out_conv_kernel(const fp16* __restrict__ ah,
                                                       const fp16* __restrict__ al,
                                                       const float* __restrict__ X,
                                                       float* __restrict__ out)
{
    __shared__ float s_w[NCC * 9 * 3];
    __shared__ float s_b[4];
    int tid = threadIdx.x;
    for (int i = tid; i < NCC * 9 * 3; i += 128) s_w[i] = g_wout[i];
    if (tid < 3) s_b[tid] = g_bout[tid];
    __syncthreads();

    int p = blockIdx.x * 128 + tid;
    int b = p >> 16;
    int y = (p >> 8) & 255;
    int x = p & 255;

    float acc0 = s_b[0], acc1 = s_b[1], acc2 = s_b[2];
    #pragma unroll
    for (int dy = 0; dy < 3; dy++) {
        int gy = y + dy - 1;
        #pragma unroll
        for (int dx = 0; dx < 3; dx++) {
            int gx = x + dx - 1;
            if (gy < 0 || gy >= HH || gx < 0 || gx >= WW) continue;
            int tap = dy * 3 + dx;
            size_t base = ((size_t)b * HH * WW + (size_t)gy * WW + gx) * NCC;
            #pragma unroll
            for (int t = 0; t < 8; t++) {
                uint4 hraw = *(const uint4*)(ah + base + t * 8);
                uint4 lraw = *(const uint4*)(al + base + t * 8);
                const fp16* hp = (const fp16*)&hraw;
                const fp16* lp = (const fp16*)&lraw;
                #pragma unroll
                for (int j = 0; j < 8; j++) {
                    int ci = t * 8 + j;
                    float v = __half2float(hp[j]) + __half2float(lp[j]);
                    const float* w = s_w + (ci * 9 + tap) * 3;
                    acc0 += v * w[0]; acc1 += v * w[1]; acc2 += v * w[2];
                }
            }
        }
    }
    float sel[3] = { selu_f(acc0), selu_f(acc1), selu_f(acc2) };

    #pragma unroll
    for (int c = 0; c < 3; c++) {
        const float* Xc = X + ((size_t)b * 3 + c) * HH * WW;
        float xv = Xc[y * WW + x];
        float l = (x > 0)       ? Xc[y * WW + x - 1] : 0.f;
        float rr = (x < WW - 1) ? Xc[y * WW + x + 1] : 0.f;
        float t = (y > 0)       ? Xc[(y - 1) * WW + x] : 0.f;
        float bt = (y < HH - 1) ? Xc[(y + 1) * WW + x] : 0.f;
        float nb_sum = l + rr + t + bt;
        float nb_cnt = (l > 0.f) + (rr > 0.f) + (t > 0.f) + (bt > 0.f);
        float mean = nb_cnt > 0.f ? nb_sum / nb_cnt : 0.f;
        float res = (xv == 0.f) ? mean : xv;
        out[((size_t)b * 3 + c) * HH * WW + (size_t)y * WW + x] = sel[c] + res;
    }
}

// ---------------- launch ----------------
extern "C" void kernel_launch(void* const* d_in, const int* in_sizes, int n_in,
                              void* d_out, int out_size)
{
    const float* X     = (const float*)d_in[0];
    const float* w_in  = (const float*)d_in[1];
    const float* b_in  = (const float*)d_in[2];
    const float* gi    = (const float*)d_in[3];
    const float* bei   = (const float*)d_in[4];
    const float* mi    = (const float*)d_in[5];
    const float* vi    = (const float*)d_in[6];
    const float* w_h   = (const float*)d_in[7];
    const float* b_h   = (const float*)d_in[8];
    const float* gh    = (const float*)d_in[9];
    const float* beh   = (const float*)d_in[10];
    const float* mh    = (const float*)d_in[11];
    const float* vh    = (const float*)d_in[12];
    const float* w_out = (const float*)d_in[13];
    const float* b_out = (const float*)d_in[14];
    const float* go    = (const float*)d_in[15];
    const float* beo   = (const float*)d_in[16];
    const float* mo    = (const float*)d_in[17];
    const float* vo    = (const float*)d_in[18];
    float* out = (float*)d_out;

    fp16 *h0, *l0, *h1, *l1;
    cudaGetSymbolAddress((void**)&h0, g_h0);
    cudaGetSymbolAddress((void**)&l0, g_l0);
    cudaGetSymbolAddress((void**)&h1, g_h1);
    cudaGetSymbolAddress((void**)&l1, g_l1);

    cudaFuncSetAttribute(hidden_mma, cudaFuncAttributeMaxDynamicSharedMemorySize, SMEM_TOT);

    prep_kernel<<<(9 * 2 * NCC * NCC + 255) / 256, 256>>>(
        w_in, b_in, gi, bei, mi, vi,
        w_h, b_h, gh, beh, mh, vh,
        w_out, b_out, go, beo, mo, vo);

    const int NPIX = BATCH * HH * WW;
    in_conv_kernel<<<NPIX / 128, 128>>>(X, h0, l0);

    dim3 hgrid(WW / 128, HH, BATCH);
    for (int lyr = 0; lyr < NHID; lyr++) {
        const fp16* sh = (lyr & 1) ? h1 : h0;
        const fp16* sl = (lyr & 1) ? l1 : l0;
        fp16* dh = (lyr & 1) ? h0 : h1;
        fp16* dl = (lyr & 1) ? l0 : l1;
        hidden_mma<<<hgrid, 256, SMEM_TOT>>>(sh, sl, dh, dl);
    }
    // NHID even -> final activations in (h0, l0)
    out_conv_kernel<<<NPIX / 128, 128>>>(h0, l0, X, out);
}

// round 9
// speedup vs baseline: 2.0155x; 1.1385x over previous
#include <cuda_runtime.h>
#include <cuda_fp16.h>
#include <cstdint>

#define BATCH 4
#define HH 256
#define WW 256
#define NCC 64
#define NHID 18
#define EPSV 1e-5f

typedef __half fp16;

// ---------------- device scratch ----------------
__device__ __align__(16) fp16 g_h0[BATCH * HH * WW * NCC];
__device__ __align__(16) fp16 g_l0[BATCH * HH * WW * NCC];
__device__ __align__(16) fp16 g_h1[BATCH * HH * WW * NCC];
__device__ __align__(16) fp16 g_l1[BATCH * HH * WW * NCC];
__device__ __align__(16) fp16 g_whx[9 * 2 * NCC * NCC];   // [tap][term][ci][co]
__device__ float g_bh[NCC];
__device__ __align__(16) float g_win[3 * 9 * NCC];
__device__ float g_bin[NCC];
__device__ __align__(16) float g_wout[NCC * 9 * 3];
__device__ float g_bout[3];

// ---------------- helpers ----------------
__device__ __forceinline__ float selu_f(float x) {
    const float sc = 1.0507009873554805f;
    const float scal = 1.7580993408473766f;
    return x > 0.f ? sc * x : scal * (expf(x) - 1.f);
}
__device__ __forceinline__ uint32_t smem_u32(const void* p) {
    uint32_t a;
    asm("{ .reg .u64 t; cvta.to.shared.u64 t, %1; cvt.u32.u64 %0, t; }" : "=r"(a) : "l"(p));
    return a;
}
__device__ __forceinline__ void cpa16(uint32_t dst, const void* src, bool pred) {
    int sz = pred ? 16 : 0;
    asm volatile("cp.async.cg.shared.global [%0], [%1], 16, %2;" :: "r"(dst), "l"(src), "r"(sz) : "memory");
}
#define CP_COMMIT() asm volatile("cp.async.commit_group;" ::: "memory")
#define CP_WAIT0()  asm volatile("cp.async.wait_group 0;" ::: "memory")

__device__ __forceinline__ void ldsm_x4(uint32_t (&r)[4], uint32_t addr) {
    asm volatile("ldmatrix.sync.aligned.m8n8.x4.shared.b16 {%0,%1,%2,%3}, [%4];"
                 : "=r"(r[0]), "=r"(r[1]), "=r"(r[2]), "=r"(r[3]) : "r"(addr));
}
__device__ __forceinline__ void ldsm_x2t(uint32_t (&r)[2], uint32_t addr) {
    asm volatile("ldmatrix.sync.aligned.m8n8.x2.trans.shared.b16 {%0,%1}, [%2];"
                 : "=r"(r[0]), "=r"(r[1]) : "r"(addr));
}
__device__ __forceinline__ void mma16816(float (&d)[4], const uint32_t (&a)[4], const uint32_t (&bb)[2]) {
    asm volatile("mma.sync.aligned.m16n8k16.row.col.f32.f16.f16.f32 "
                 "{%0,%1,%2,%3}, {%4,%5,%6,%7}, {%8,%9}, {%0,%1,%2,%3};"
                 : "+f"(d[0]), "+f"(d[1]), "+f"(d[2]), "+f"(d[3])
                 : "r"(a[0]), "r"(a[1]), "r"(a[2]), "r"(a[3]), "r"(bb[0]), "r"(bb[1]));
}

// smem layout: bias | A tiles [term(2)][row(4)] x 130px x 64ci | W double-buffer
static constexpr int A_TILE = 132 * 128;                  // bytes per tile
static constexpr int SMEM_A = 1024;
static constexpr int SMEM_WB = SMEM_A + 8 * A_TILE;       // 1024 + 135168 = 136192
static constexpr int WSTAGE = 2 * NCC * NCC * 2;          // 16384 bytes per tap
static constexpr int SMEM_TOT = SMEM_WB + 2 * WSTAGE;     // 168960

// ---------------- prep: fold BN, split weights to fp16 hi/lo ----------------
__global__ void prep_kernel(
    const float* __restrict__ w_in, const float* __restrict__ b_in,
    const float* __restrict__ g_in, const float* __restrict__ be_in,
    const float* __restrict__ m_in, const float* __restrict__ v_in,
    const float* __restrict__ w_h,  const float* __restrict__ b_h,
    const float* __restrict__ g_h,  const float* __restrict__ be_h,
    const float* __restrict__ m_h,  const float* __restrict__ v_h,
    const float* __restrict__ w_out, const float* __restrict__ b_out,
    const float* __restrict__ g_out, const float* __restrict__ be_out,
    const float* __restrict__ m_out, const float* __restrict__ v_out)
{
    int idx = blockIdx.x * blockDim.x + threadIdx.x;
    if (idx < 9 * 2 * NCC * NCC) {        // [tap][term][ci][co]
        int co = idx & 63;
        int ci = (idx >> 6) & 63;
        int term = (idx >> 12) & 1;
        int tap = idx >> 13;
        float s = g_h[co] * rsqrtf(v_h[co] + EPSV);
        float wf = w_h[(co * NCC + ci) * 9 + tap] * s;
        fp16 hi = __float2half_rn(wf);
        g_whx[idx] = (term == 0) ? hi : __float2half_rn(wf - __half2float(hi));
    }
    if (idx < 3 * 9 * NCC) {
        int co = idx & 63;
        int rest = idx >> 6;
        int tap = rest % 9;
        int ci = rest / 9;
        float s = g_in[co] * rsqrtf(v_in[co] + EPSV);
        g_win[idx] = w_in[(co * 3 + ci) * 9 + tap] * s;
    }
    if (idx < NCC * 9 * 3) {
        int co = idx % 3;
        int rest = idx / 3;
        int tap = rest % 9;
        int ci = rest / 9;
        float s = g_out[co] * rsqrtf(v_out[co] + EPSV);
        g_wout[idx] = w_out[(co * NCC + ci) * 9 + tap] * s;
    }
    if (idx < NCC) {
        g_bh[idx]  = (b_h[idx]  - m_h[idx])  * (g_h[idx]  * rsqrtf(v_h[idx]  + EPSV)) + be_h[idx];
        g_bin[idx] = (b_in[idx] - m_in[idx]) * (g_in[idx] * rsqrtf(v_in[idx] + EPSV)) + be_in[idx];
    }
    if (idx < 3) {
        g_bout[idx] = (b_out[idx] - m_out[idx]) * (g_out[idx] * rsqrtf(v_out[idx] + EPSV)) + be_out[idx];
    }
}

// ---------------- input conv 3->64 + BN + SELU, NCHW -> NHWC fp16 hi/lo ----------------
__global__ __launch_bounds__(128) void in_conv_kernel(const float* __restrict__ X,
                                                      fp16* __restrict__ oh, fp16* __restrict__ ol)
{
    __shared__ __align__(16) float s_w[3 * 9 * NCC];
    __shared__ __align__(16) float s_b[NCC];
    int tid = threadIdx.x;
    for (int i = tid; i < 3 * 9 * NCC; i += 128) s_w[i] = g_win[i];
    if (tid < NCC) s_b[tid] = g_bin[tid];
    __syncthreads();

    int p = blockIdx.x * 128 + tid;
    int b = p >> 16;
    int y = (p >> 8) & 255;
    int x = p & 255;
    const float* Xb = X + (size_t)b * 3 * HH * WW;

    float4 acc[16];
    #pragma unroll
    for (int q = 0; q < 16; q++) acc[q] = ((const float4*)s_b)[q];

    #pragma unroll
    for (int ci = 0; ci < 3; ci++) {
        #pragma unroll
        for (int dy = 0; dy < 3; dy++) {
            int gy = y + dy - 1;
            #pragma unroll
            for (int dx = 0; dx < 3; dx++) {
                int gx = x + dx - 1;
                float v = 0.f;
                if (gy >= 0 && gy < HH && gx >= 0 && gx < WW)
                    v = Xb[ci * HH * WW + gy * WW + gx];
                const float4* w4 = (const float4*)(s_w + (ci * 9 + dy * 3 + dx) * NCC);
                #pragma unroll
                for (int q = 0; q < 16; q++) {
                    float4 w = w4[q];
                    acc[q].x += v * w.x; acc[q].y += v * w.y;
                    acc[q].z += v * w.z; acc[q].w += v * w.w;
                }
            }
        }
    }
    fp16 hv[64], lv[64];
    #pragma unroll
    for (int q = 0; q < 16; q++) {
        float vv[4] = { acc[q].x, acc[q].y, acc[q].z, acc[q].w };
        #pragma unroll
        for (int j = 0; j < 4; j++) {
            float v = selu_f(vv[j]);
            fp16 h = __float2half_rn(v);
            hv[q * 4 + j] = h;
            lv[q * 4 + j] = __float2half_rn(v - __half2float(h));
        }
    }
    #pragma unroll
    for (int t = 0; t < 8; t++) {
        *(uint4*)(oh + (size_t)p * NCC + t * 8) = *(uint4*)(hv + t * 8);
        *(uint4*)(ol + (size_t)p * NCC + t * 8) = *(uint4*)(lv + t * 8);
    }
}

// ---------------- hidden conv 64->64 via mma.sync HMMA (3-term fp16 split) ----------------
// CTA: 256 thr = 8 warps; 2 output rows x 128 px strip; all 64 co.
// Warps 0-3: row y0, px base (w&3)*32, M=32 per warp. Warps 4-7: row y0+1.
// smem A: [term(2)][inrow(4)] x 130 px x 64 ci fp16, 16B-group swizzle.
// W streamed per tap: [term][ci][co] fp16, double buffered.
__global__ __launch_bounds__(256, 1) void hidden_mma(const fp16* __restrict__ ah, const fp16* __restrict__ al,
                                                     fp16* __restrict__ oh, fp16* __restrict__ ol)
{
    extern __shared__ char smem[];
    float* s_bias = (float*)smem;
    uint32_t sAu = smem_u32(smem + SMEM_A);
    uint32_t sWu = smem_u32(smem + SMEM_WB);
    int tid = threadIdx.x;
    int x0 = blockIdx.x * 128;
    int y0 = blockIdx.y * 2;
    int b  = blockIdx.z;

    if (tid < 64) s_bias[tid] = g_bh[tid];

    // --- A halo tile loads: 8 tiles (term x 4 input rows) x 130 px x 8 groups of 16B ---
    for (int j = tid; j < 8 * 130 * 8; j += 256) {
        int g = j & 7;
        int p = (j >> 3) % 130;
        int t3 = (j >> 3) / 130;            // term*4 + ri
        int ri = t3 & 3;
        int gx = x0 - 1 + p, gy = y0 - 1 + ri;
        bool v = (gx >= 0 && gx < WW && gy >= 0 && gy < HH);
        int gxc = v ? gx : 0;
        int gyc = (gy >= 0 && gy < HH) ? gy : 0;
        const fp16* base = (t3 >= 4) ? al : ah;
        const fp16* src = base + ((size_t)((b * HH + gyc) * WW) + gxc) * NCC + g * 8;
        uint32_t dst = sAu + t3 * A_TILE + p * 128 + ((g ^ (p & 7)) << 4);
        cpa16(dst, src, v);
    }
    // --- stage W tap 0 into buf 0 ---
    {
        const char* src = (const char*)g_whx;
        for (int j = tid; j < 1024; j += 256) {
            int g = j & 7, ci = (j >> 3) & 63, term = j >> 9;
            uint32_t dst = sWu + term * 8192 + ci * 128 + ((g ^ (ci & 7)) << 4);
            cpa16(dst, src + term * 8192 + ci * 128 + g * 16, true);
        }
    }
    CP_COMMIT();

    float acc[2][8][4];
    #pragma unroll
    for (int mt = 0; mt < 2; mt++)
        #pragma unroll
        for (int n0 = 0; n0 < 8; n0++)
            #pragma unroll
            for (int k = 0; k < 4; k++) acc[mt][n0][k] = 0.f;

    int lane = tid & 31;
    int w = tid >> 5;
    int r = w >> 2;                 // output row within CTA (0/1)
    int mp = (w & 3) * 32;          // warp's 32-px base
    int mat = lane >> 3, rr = lane & 7;
    int mrow = ((mat & 1) << 3) + rr;   // A m_local within m16 tile
    int kh = mat >> 1;                  // A k-half
    int l16 = lane & 15;                // B ci row within 16

    int wbuf = 0;
    for (int tap = 0; tap < 9; ++tap) {
        CP_WAIT0();
        __syncthreads();
        if (tap < 8) {
            const char* src = (const char*)g_whx + (tap + 1) * WSTAGE;
            uint32_t dstb = sWu + (wbuf ^ 1) * WSTAGE;
            for (int j = tid; j < 1024; j += 256) {
                int g = j & 7, ci = (j >> 3) & 63, term = j >> 9;
                uint32_t dst = dstb + term * 8192 + ci * 128 + ((g ^ (ci & 7)) << 4);
                cpa16(dst, src + term * 8192 + ci * 128 + g * 16, true);
            }
            CP_COMMIT();
        }
        int dy = tap / 3, dx = tap % 3;
        int trow = r + dy;                  // input-row tile index 0..3

        #pragma unroll
        for (int kc = 0; kc < 4; ++kc) {
            uint32_t a_hi[2][4], a_lo[2][4];
            #pragma unroll
            for (int mt = 0; mt < 2; mt++) {
                int s = mp + mt * 16 + mrow + dx;    // strip px 0..129
                int g = kc * 2 + kh;
                uint32_t arow = (uint32_t)(trow * A_TILE + s * 128 + ((g ^ (s & 7)) << 4));
                ldsm_x4(a_hi[mt], sAu + arow);
                ldsm_x4(a_lo[mt], sAu + 4 * A_TILE + arow);
            }
            int ci = kc * 16 + l16;
            uint32_t wrow = sWu + wbuf * WSTAGE + ci * 128;
            uint32_t sw = (ci & 7) << 4;
            #pragma unroll
            for (int n0 = 0; n0 < 8; ++n0) {
                uint32_t bh2[2], bl2[2];
                ldsm_x2t(bh2, wrow + ((n0 << 4) ^ sw));
                ldsm_x2t(bl2, wrow + 8192 + ((n0 << 4) ^ sw));
                mma16816(acc[0][n0], a_hi[0], bh2);
                mma16816(acc[1][n0], a_hi[1], bh2);
                mma16816(acc[0][n0], a_lo[0], bh2);
                mma16816(acc[1][n0], a_lo[1], bh2);
                mma16816(acc[0][n0], a_hi[0], bl2);
                mma16816(acc[1][n0], a_hi[1], bl2);
            }
        }
        __syncthreads();
        wbuf ^= 1;
    }

    // --- epilogue: bias + SELU + fp16 hi/lo split, store NHWC ---
    int q = lane >> 2;
    int cp2 = (lane & 3) << 1;
    int gy = y0 + r;
    #pragma unroll
    for (int mt = 0; mt < 2; ++mt) {
        #pragma unroll
        for (int n0 = 0; n0 < 8; ++n0) {
            float b0 = s_bias[n0 * 8 + cp2];
            float b1 = s_bias[n0 * 8 + cp2 + 1];
            #pragma unroll
            for (int hr = 0; hr < 2; ++hr) {
                int px = mp + mt * 16 + q + hr * 8;
                float v0 = acc[mt][n0][hr * 2 + 0] + b0;
                float v1 = acc[mt][n0][hr * 2 + 1] + b1;
                v0 = selu_f(v0);
                v1 = selu_f(v1);
                fp16 h0 = __float2half_rn(v0);
                fp16 h1 = __float2half_rn(v1);
                fp16 lo0 = __float2half_rn(v0 - __half2float(h0));
                fp16 lo1 = __float2half_rn(v1 - __half2float(h1));
                size_t off = ((size_t)((b * HH + gy) * WW) + (x0 + px)) * NCC + n0 * 8 + cp2;
                *(__half2*)(oh + off) = __halves2half2(h0, h1);
                *(__half2*)(ol + off) = __halves2half2(lo0, lo1);
            }
        }
    }
}

// ---------------- output conv 64->3 + BN + SELU + bayer residual ----------------
__global__ __launch_bounds__(128) void out_conv_kernel(const fp16* __restrict__ ah,
                                                       const fp16* __restrict__ al,
                                                       const float* __restrict__ X,
                                                       float* __restrict__ out)
{
    __shared__ float s_w[NCC * 9 * 3];
    __shared__ float s_b[4];
    int tid = threadIdx.x;
    for (int i = tid; i < NCC * 9 * 3; i += 128) s_w[i] = g_wout[i];
    if (tid < 3) s_b[tid] = g_bout[tid];
    __syncthreads();

    int p = blockIdx.x * 128 + tid;
    int b = p >> 16;
    int y = (p >> 8) & 255;
    int x = p & 255;

    float acc0 = s_b[0], acc1 = s_b[1], acc2 = s_b[2];
    #pragma unroll
    for (int dy = 0; dy < 3; dy++) {
        int gy = y + dy - 1;
        #pragma unroll
        for (int dx = 0; dx < 3; dx++) {
            int gx = x + dx - 1;
            if (gy < 0 || gy >= HH || gx < 0 || gx >= WW) continue;
            int tap = dy * 3 + dx;
            size_t base = ((size_t)b * HH * WW + (size_t)gy * WW + gx) * NCC;
            #pragma unroll
            for (int t = 0; t < 8; t++) {
                uint4 hraw = *(const uint4*)(ah + base + t * 8);
                uint4 lraw = *(const uint4*)(al + base + t * 8);
                const fp16* hp = (const fp16*)&hraw;
                const fp16* lp = (const fp16*)&lraw;
                #pragma unroll
                for (int j = 0; j < 8; j++) {
                    int ci = t * 8 + j;
                    float v = __half2float(hp[j]) + __half2float(lp[j]);
                    const float* w = s_w + (ci * 9 + tap) * 3;
                    acc0 += v * w[0]; acc1 += v * w[1]; acc2 += v * w[2];
                }
            }
        }
    }
    float sel[3] = { selu_f(acc0), selu_f(acc1), selu_f(acc2) };

    #pragma unroll
    for (int c = 0; c < 3; c++) {
        const float* Xc = X + ((size_t)b * 3 + c) * HH * WW;
        float xv = Xc[y * WW + x];
        float l = (x > 0)       ? Xc[y * WW + x - 1] : 0.f;
        float rr = (x < WW - 1) ? Xc[y * WW + x + 1] : 0.f;
        float t = (y > 0)       ? Xc[(y - 1) * WW + x] : 0.f;
        float bt = (y < HH - 1) ? Xc[(y + 1) * WW + x] : 0.f;
        float nb_sum = l + rr + t + bt;
        float nb_cnt = (l > 0.f) + (rr > 0.f) + (t > 0.f) + (bt > 0.f);
        float mean = nb_cnt > 0.f ? nb_sum / nb_cnt : 0.f;
        float res = (xv == 0.f) ? mean : xv;
        out[((size_t)b * 3 + c) * HH * WW + (size_t)y * WW + x] = sel[c] + res;
    }
}

// ---------------- launch ----------------
extern "C" void kernel_launch(void* const* d_in, const int* in_sizes, int n_in,
                              void* d_out, int out_size)
{
    const float* X     = (const float*)d_in[0];
    const float* w_in  = (const float*)d_in[1];
    const float* b_in  = (const float*)d_in[2];
    const float* gi    = (const float*)d_in[3];
    const float* bei   = (const float*)d_in[4];
    const float* mi    = (const float*)d_in[5];
    const float* vi    = (const float*)d_in[6];
    const float* w_h   = (const float*)d_in[7];
    const float* b_h   = (const float*)d_in[8];
    const float* gh    = (const float*)d_in[9];
    const float* beh   = (const float*)d_in[10];
    const float* mh    = (const float*)d_in[11];
    const float* vh    = (const float*)d_in[12];
    const float* w_out = (const float*)d_in[13];
    const float* b_out = (const float*)d_in[14];
    const float* go    = (const float*)d_in[15];
    const float* beo   = (const float*)d_in[16];
    const float* mo    = (const float*)d_in[17];
    const float* vo    = (const float*)d_in[18];
    float* out = (float*)d_out;

    fp16 *h0, *l0, *h1, *l1;
    cudaGetSymbolAddress((void**)&h0, g_h0);
    cudaGetSymbolAddress((void**)&l0, g_l0);
    cudaGetSymbolAddress((void**)&h1, g_h1);
    cudaGetSymbolAddress((void**)&l1, g_l1);

    cudaFuncSetAttribute(hidden_mma, cudaFuncAttributeMaxDynamicSharedMemorySize, SMEM_TOT);

    prep_kernel<<<(9 * 2 * NCC * NCC + 255) / 256, 256>>>(
        w_in, b_in, gi, bei, mi, vi,
        w_h, b_h, gh, beh, mh, vh,
        w_out, b_out, go, beo, mo, vo);

    const int NPIX = BATCH * HH * WW;
    in_conv_kernel<<<NPIX / 128, 128>>>(X, h0, l0);

    dim3 hgrid(WW / 128, HH / 2, BATCH);
    for (int lyr = 0; lyr < NHID; lyr++) {
        const fp16* sh = (lyr & 1) ? h1 : h0;
        const fp16* sl = (lyr & 1) ? l1 : l0;
        fp16* dh = (lyr & 1) ? h0 : h1;
        fp16* dl = (lyr & 1) ? l0 : l1;
        hidden_mma<<<hgrid, 256, SMEM_TOT>>>(sh, sl, dh, dl);
    }
    // NHID even -> final activations in (h0, l0)
    out_conv_kernel<<<NPIX / 128, 128>>>(h0, l0, X, out);
}

// round 12
// speedup vs baseline: 2.1336x; 1.0586x over previous
#include <cuda_runtime.h>
#include <cuda_fp16.h>
#include <cstdint>

#define BATCH 4
#define HH 256
#define WW 256
#define NCC 64
#define NHID 18
#define EPSV 1e-5f

typedef __half fp16;

// ---------------- device scratch ----------------
__device__ __align__(16) fp16 g_h0[BATCH * HH * WW * NCC];
__device__ __align__(16) fp16 g_l0[BATCH * HH * WW * NCC];
__device__ __align__(16) fp16 g_h1[BATCH * HH * WW * NCC];
__device__ __align__(16) fp16 g_l1[BATCH * HH * WW * NCC];
__device__ __align__(16) fp16 g_whx[9 * 2 * NCC * NCC];   // [tap][term][ci][co]
__device__ float g_bh[NCC];
__device__ __align__(16) float g_win[3 * 9 * NCC];
__device__ float g_bin[NCC];
__device__ __align__(16) float g_wout[NCC * 9 * 3];
__device__ float g_bout[3];

// ---------------- helpers ----------------
__device__ __forceinline__ float selu_f(float x) {
    const float sc = 1.0507009873554805f;
    const float scal = 1.7580993408473766f;
    return x > 0.f ? sc * x : scal * (expf(x) - 1.f);
}
__device__ __forceinline__ uint32_t smem_u32(const void* p) {
    uint32_t a;
    asm("{ .reg .u64 t; cvta.to.shared.u64 t, %1; cvt.u32.u64 %0, t; }" : "=r"(a) : "l"(p));
    return a;
}
__device__ __forceinline__ void cpa16(uint32_t dst, const void* src, bool pred) {
    int sz = pred ? 16 : 0;
    asm volatile("cp.async.cg.shared.global [%0], [%1], 16, %2;" :: "r"(dst), "l"(src), "r"(sz) : "memory");
}
#define CP_COMMIT() asm volatile("cp.async.commit_group;" ::: "memory")
#define CP_WAIT0()  asm volatile("cp.async.wait_group 0;" ::: "memory")

__device__ __forceinline__ void ldsm_x4(uint32_t (&r)[4], uint32_t addr) {
    asm volatile("ldmatrix.sync.aligned.m8n8.x4.shared.b16 {%0,%1,%2,%3}, [%4];"
                 : "=r"(r[0]), "=r"(r[1]), "=r"(r[2]), "=r"(r[3]) : "r"(addr));
}
__device__ __forceinline__ void ldsm_x2t(uint32_t (&r)[2], uint32_t addr) {
    asm volatile("ldmatrix.sync.aligned.m8n8.x2.trans.shared.b16 {%0,%1}, [%2];"
                 : "=r"(r[0]), "=r"(r[1]) : "r"(addr));
}
__device__ __forceinline__ void mma16816(float (&d)[4], const uint32_t (&a)[4], const uint32_t (&bb)[2]) {
    asm volatile("mma.sync.aligned.m16n8k16.row.col.f32.f16.f16.f32 "
                 "{%0,%1,%2,%3}, {%4,%5,%6,%7}, {%8,%9}, {%0,%1,%2,%3};"
                 : "+f"(d[0]), "+f"(d[1]), "+f"(d[2]), "+f"(d[3])
                 : "r"(a[0]), "r"(a[1]), "r"(a[2]), "r"(a[3]), "r"(bb[0]), "r"(bb[1]));
}

// smem layout: bias | A tiles [term(2)][inrow(4)] x 130px x 64ci | W double-buffer
static constexpr int A_TILE = 130 * 128;                  // 16640 bytes per tile
static constexpr int SMEM_A = 1024;
static constexpr int SMEM_WB = SMEM_A + 8 * A_TILE;       // 1024 + 133120 = 134144
static constexpr int WSTAGE = 2 * NCC * NCC * 2;          // 16384 bytes per tap
static constexpr int SMEM_TOT = SMEM_WB + 2 * WSTAGE;     // 166912

// ---------------- prep: fold BN, split weights to fp16 hi/lo ----------------
__global__ void prep_kernel(
    const float* __restrict__ w_in, const float* __restrict__ b_in,
    const float* __restrict__ g_in, const float* __restrict__ be_in,
    const float* __restrict__ m_in, const float* __restrict__ v_in,
    const float* __restrict__ w_h,  const float* __restrict__ b_h,
    const float* __restrict__ g_h,  const float* __restrict__ be_h,
    const float* __restrict__ m_h,  const float* __restrict__ v_h,
    const float* __restrict__ w_out, const float* __restrict__ b_out,
    const float* __restrict__ g_out, const float* __restrict__ be_out,
    const float* __restrict__ m_out, const float* __restrict__ v_out)
{
    int idx = blockIdx.x * blockDim.x + threadIdx.x;
    if (idx < 9 * 2 * NCC * NCC) {        // [tap][term][ci][co]
        int co = idx & 63;
        int ci = (idx >> 6) & 63;
        int term = (idx >> 12) & 1;
        int tap = idx >> 13;
        float s = g_h[co] * rsqrtf(v_h[co] + EPSV);
        float wf = w_h[(co * NCC + ci) * 9 + tap] * s;
        fp16 hi = __float2half_rn(wf);
        g_whx[idx] = (term == 0) ? hi : __float2half_rn(wf - __half2float(hi));
    }
    if (idx < 3 * 9 * NCC) {
        int co = idx & 63;
        int rest = idx >> 6;
        int tap = rest % 9;
        int ci = rest / 9;
        float s = g_in[co] * rsqrtf(v_in[co] + EPSV);
        g_win[idx] = w_in[(co * 3 + ci) * 9 + tap] * s;
    }
    if (idx < NCC * 9 * 3) {
        int co = idx % 3;
        int rest = idx / 3;
        int tap = rest % 9;
        int ci = rest / 9;
        float s = g_out[co] * rsqrtf(v_out[co] + EPSV);
        g_wout[idx] = w_out[(co * NCC + ci) * 9 + tap] * s;
    }
    if (idx < NCC) {
        g_bh[idx]  = (b_h[idx]  - m_h[idx])  * (g_h[idx]  * rsqrtf(v_h[idx]  + EPSV)) + be_h[idx];
        g_bin[idx] = (b_in[idx] - m_in[idx]) * (g_in[idx] * rsqrtf(v_in[idx] + EPSV)) + be_in[idx];
    }
    if (idx < 3) {
        g_bout[idx] = (b_out[idx] - m_out[idx]) * (g_out[idx] * rsqrtf(v_out[idx] + EPSV)) + be_out[idx];
    }
}

// ---------------- input conv 3->64 + BN + SELU, NCHW -> NHWC fp16 hi/lo ----------------
__global__ __launch_bounds__(128) void in_conv_kernel(const float* __restrict__ X,
                                                      fp16* __restrict__ oh, fp16* __restrict__ ol)
{
    __shared__ __align__(16) float s_w[3 * 9 * NCC];
    __shared__ __align__(16) float s_b[NCC];
    int tid = threadIdx.x;
    for (int i = tid; i < 3 * 9 * NCC; i += 128) s_w[i] = g_win[i];
    if (tid < NCC) s_b[tid] = g_bin[tid];
    __syncthreads();

    int p = blockIdx.x * 128 + tid;
    int b = p >> 16;
    int y = (p >> 8) & 255;
    int x = p & 255;
    const float* Xb = X + (size_t)b * 3 * HH * WW;

    float4 acc[16];
    #pragma unroll
    for (int q = 0; q < 16; q++) acc[q] = ((const float4*)s_b)[q];

    #pragma unroll
    for (int ci = 0; ci < 3; ci++) {
        #pragma unroll
        for (int dy = 0; dy < 3; dy++) {
            int gy = y + dy - 1;
            #pragma unroll
            for (int dx = 0; dx < 3; dx++) {
                int gx = x + dx - 1;
                float v = 0.f;
                if (gy >= 0 && gy < HH && gx >= 0 && gx < WW)
                    v = Xb[ci * HH * WW + gy * WW + gx];
                const float4* w4 = (const float4*)(s_w + (ci * 9 + dy * 3 + dx) * NCC);
                #pragma unroll
                for (int q = 0; q < 16; q++) {
                    float4 w = w4[q];
                    acc[q].x += v * w.x; acc[q].y += v * w.y;
                    acc[q].z += v * w.z; acc[q].w += v * w.w;
                }
            }
        }
    }
    fp16 hv[64], lv[64];
    #pragma unroll
    for (int q = 0; q < 16; q++) {
        float vv[4] = { acc[q].x, acc[q].y, acc[q].z, acc[q].w };
        #pragma unroll
        for (int j = 0; j < 4; j++) {
            float v = selu_f(vv[j]);
            fp16 h = __float2half_rn(v);
            hv[q * 4 + j] = h;
            lv[q * 4 + j] = __float2half_rn(v - __half2float(h));
        }
    }
    #pragma unroll
    for (int t = 0; t < 8; t++) {
        *(uint4*)(oh + (size_t)p * NCC + t * 8) = *(uint4*)(hv + t * 8);
        *(uint4*)(ol + (size_t)p * NCC + t * 8) = *(uint4*)(lv + t * 8);
    }
}

// ---------------- hidden conv 64->64 via mma.sync HMMA (3-term fp16 split) ----------------
// CTA: 512 thr = 16 warps; 2 output rows x 128 px strip; 64 co.
// Warp = (nh: co half) x (r: row) x (st: 32-px strip); per-warp tile M=32, N=32.
// smem A: [term(2)][inrow(4)] x 130 px x 64 ci fp16, 16B-group swizzle.
// W streamed per tap: [term][ci][co] fp16, double buffered.
__global__ __launch_bounds__(512, 1) void hidden_mma(const fp16* __restrict__ ah, const fp16* __restrict__ al,
                                                     fp16* __restrict__ oh, fp16* __restrict__ ol)
{
    extern __shared__ char smem[];
    float* s_bias = (float*)smem;
    uint32_t sAu = smem_u32(smem + SMEM_A);
    uint32_t sWu = smem_u32(smem + SMEM_WB);
    int tid = threadIdx.x;
    int x0 = blockIdx.x * 128;
    int y0 = blockIdx.y * 2;
    int b  = blockIdx.z;

    if (tid < 64) s_bias[tid] = g_bh[tid];

    // --- A halo tile loads: 8 tiles (term x 4 input rows) x 130 px x 8 groups of 16B ---
    for (int j = tid; j < 8 * 130 * 8; j += 512) {
        int g = j & 7;
        int p = (j >> 3) % 130;
        int t3 = (j >> 3) / 130;            // term*4 + ri
        int ri = t3 & 3;
        int gx = x0 - 1 + p, gy = y0 - 1 + ri;
        bool v = (gx >= 0 && gx < WW && gy >= 0 && gy < HH);
        int gxc = v ? gx : 0;
        int gyc = (gy >= 0 && gy < HH) ? gy : 0;
        const fp16* base = (t3 >= 4) ? al : ah;
        const fp16* src = base + ((size_t)((b * HH + gyc) * WW) + gxc) * NCC + g * 8;
        uint32_t dst = sAu + t3 * A_TILE + p * 128 + ((g ^ (p & 7)) << 4);
        cpa16(dst, src, v);
    }
    // --- stage W tap 0 into buf 0 ---
    {
        const char* src = (const char*)g_whx;
        for (int j = tid; j < 1024; j += 512) {
            int g = j & 7, ci = (j >> 3) & 63, term = j >> 9;
            uint32_t dst = sWu + term * 8192 + ci * 128 + ((g ^ (ci & 7)) << 4);
            cpa16(dst, src + term * 8192 + ci * 128 + g * 16, true);
        }
    }
    CP_COMMIT();

    float acc[2][4][4];
    #pragma unroll
    for (int mt = 0; mt < 2; mt++)
        #pragma unroll
        for (int n0 = 0; n0 < 4; n0++)
            #pragma unroll
            for (int k = 0; k < 4; k++) acc[mt][n0][k] = 0.f;

    int lane = tid & 31;
    int w = tid >> 5;
    int nh = w >> 3;                // co half (0/1)
    int r = (w >> 2) & 1;           // output row within CTA (0/1)
    int mp = (w & 3) * 32;          // warp's 32-px base
    int mat = lane >> 3, rr = lane & 7;
    int mrow = ((mat & 1) << 3) + rr;   // A m_local within m16 tile
    int kh = mat >> 1;                  // A k-half
    int l16 = lane & 15;                // B ci row within 16

    int wbuf = 0;
    for (int tap = 0; tap < 9; ++tap) {
        CP_WAIT0();
        __syncthreads();
        if (tap < 8) {
            const char* src = (const char*)g_whx + (tap + 1) * WSTAGE;
            uint32_t dstb = sWu + (wbuf ^ 1) * WSTAGE;
            for (int j = tid; j < 1024; j += 512) {
                int g = j & 7, ci = (j >> 3) & 63, term = j >> 9;
                uint32_t dst = dstb + term * 8192 + ci * 128 + ((g ^ (ci & 7)) << 4);
                cpa16(dst, src + term * 8192 + ci * 128 + g * 16, true);
            }
            CP_COMMIT();
        }
        int dy = tap / 3, dx = tap % 3;
        int trow = r + dy;                  // input-row tile index 0..3

        #pragma unroll
        for (int kc = 0; kc < 4; ++kc) {
            uint32_t a_hi[2][4], a_lo[2][4];
            #pragma unroll
            for (int mt = 0; mt < 2; mt++) {
                int s = mp + mt * 16 + mrow + dx;    // strip px 0..129
                int g = kc * 2 + kh;
                uint32_t arow = (uint32_t)(trow * A_TILE + s * 128 + ((g ^ (s & 7)) << 4));
                ldsm_x4(a_hi[mt], sAu + arow);
                ldsm_x4(a_lo[mt], sAu + 4 * A_TILE + arow);
            }
            int ci = kc * 16 + l16;
            uint32_t wrow = sWu + wbuf * WSTAGE + ci * 128;
            uint32_t sw = (ci & 7) << 4;
            #pragma unroll
            for (int n0 = 0; n0 < 4; ++n0) {
                int n0g = nh * 4 + n0;
                uint32_t bh2[2], bl2[2];
                ldsm_x2t(bh2, wrow + ((n0g << 4) ^ sw));
                ldsm_x2t(bl2, wrow + 8192 + ((n0g << 4) ^ sw));
                mma16816(acc[0][n0], a_hi[0], bh2);
                mma16816(acc[1][n0], a_hi[1], bh2);
                mma16816(acc[0][n0], a_lo[0], bh2);
                mma16816(acc[1][n0], a_lo[1], bh2);
                mma16816(acc[0][n0], a_hi[0], bl2);
                mma16816(acc[1][n0], a_hi[1], bl2);
            }
        }
        __syncthreads();
        wbuf ^= 1;
    }

    // --- epilogue: bias + SELU + fp16 hi/lo split, store NHWC ---
    int q = lane >> 2;
    int cp2 = (lane & 3) << 1;
    int gy = y0 + r;
    #pragma unroll
    for (int mt = 0; mt < 2; ++mt) {
        #pragma unroll
        for (int n0 = 0; n0 < 4; ++n0) {
            int cb = nh * 32 + n0 * 8 + cp2;
            float b0 = s_bias[cb];
            float b1 = s_bias[cb + 1];
            #pragma unroll
            for (int hr = 0; hr < 2; ++hr) {
                int px = mp + mt * 16 + q + hr * 8;
                float v0 = acc[mt][n0][hr * 2 + 0] + b0;
                float v1 = acc[mt][n0][hr * 2 + 1] + b1;
                v0 = selu_f(v0);
                v1 = selu_f(v1);
                fp16 h0 = __float2half_rn(v0);
                fp16 h1 = __float2half_rn(v1);
                fp16 lo0 = __float2half_rn(v0 - __half2float(h0));
                fp16 lo1 = __float2half_rn(v1 - __half2float(h1));
                size_t off = ((size_t)((b * HH + gy) * WW) + (x0 + px)) * NCC + cb;
                *(__half2*)(oh + off) = __halves2half2(h0, h1);
                *(__half2*)(ol + off) = __halves2half2(lo0, lo1);
            }
        }
    }
}

// ---------------- output conv 64->3 + BN + SELU + bayer residual ----------------
__global__ __launch_bounds__(128) void out_conv_kernel(const fp16* __restrict__ ah,
                                                       const fp16* __restrict__ al,
                                                       const float* __restrict__ X,
                                                       float* __restrict__ out)
{
    __shared__ float s_w[NCC * 9 * 3];
    __shared__ float s_b[4];
    int tid = threadIdx.x;
    for (int i = tid; i < NCC * 9 * 3; i += 128) s_w[i] = g_wout[i];
    if (tid < 3) s_b[tid] = g_bout[tid];
    __syncthreads();

    int p = blockIdx.x * 128 + tid;
    int b = p >> 16;
    int y = (p >> 8) & 255;
    int x = p & 255;

    float acc0 = s_b[0], acc1 = s_b[1], acc2 = s_b[2];
    #pragma unroll
    for (int dy = 0; dy < 3; dy++) {
        int gy = y + dy - 1;
        #pragma unroll
        for (int dx = 0; dx < 3; dx++) {
            int gx = x + dx - 1;
            if (gy < 0 || gy >= HH || gx < 0 || gx >= WW) continue;
            int tap = dy * 3 + dx;
            size_t base = ((size_t)b * HH * WW + (size_t)gy * WW + gx) * NCC;
            #pragma unroll
            for (int t = 0; t < 8; t++) {
                uint4 hraw = *(const uint4*)(ah + base + t * 8);
                uint4 lraw = *(const uint4*)(al + base + t * 8);
                const fp16* hp = (const fp16*)&hraw;
                const fp16* lp = (const fp16*)&lraw;
                #pragma unroll
                for (int j = 0; j < 8; j++) {
                    int ci = t * 8 + j;
                    float v = __half2float(hp[j]) + __half2float(lp[j]);
                    const float* w = s_w + (ci * 9 + tap) * 3;
                    acc0 += v * w[0]; acc1 += v * w[1]; acc2 += v * w[2];
                }
            }
        }
    }
    float sel[3] = { selu_f(acc0), selu_f(acc1), selu_f(acc2) };

    #pragma unroll
    for (int c = 0; c < 3; c++) {
        const float* Xc = X + ((size_t)b * 3 + c) * HH * WW;
        float xv = Xc[y * WW + x];
        float l = (x > 0)       ? Xc[y * WW + x - 1] : 0.f;
        float rr = (x < WW - 1) ? Xc[y * WW + x + 1] : 0.f;
        float t = (y > 0)       ? Xc[(y - 1) * WW + x] : 0.f;
        float bt = (y < HH - 1) ? Xc[(y + 1) * WW + x] : 0.f;
        float nb_sum = l + rr + t + bt;
        float nb_cnt = (l > 0.f) + (rr > 0.f) + (t > 0.f) + (bt > 0.f);
        float mean = nb_cnt > 0.f ? nb_sum / nb_cnt : 0.f;
        float res = (xv == 0.f) ? mean : xv;
        out[((size_t)b * 3 + c) * HH * WW + (size_t)y * WW + x] = sel[c] + res;
    }
}

// ---------------- launch ----------------
extern "C" void kernel_launch(void* const* d_in, const int* in_sizes, int n_in,
                              void* d_out, int out_size)
{
    const float* X     = (const float*)d_in[0];
    const float* w_in  = (const float*)d_in[1];
    const float* b_in  = (const float*)d_in[2];
    const float* gi    = (const float*)d_in[3];
    const float* bei   = (const float*)d_in[4];
    const float* mi    = (const float*)d_in[5];
    const float* vi    = (const float*)d_in[6];
    const float* w_h   = (const float*)d_in[7];
    const float* b_h   = (const float*)d_in[8];
    const float* gh    = (const float*)d_in[9];
    const float* beh   = (const float*)d_in[10];
    const float* mh    = (const float*)d_in[11];
    const float* vh    = (const float*)d_in[12];
    const float* w_out = (const float*)d_in[13];
    const float* b_out = (const float*)d_in[14];
    const float* go    = (const float*)d_in[15];
    const float* beo   = (const float*)d_in[16];
    const float* mo    = (const float*)d_in[17];
    const float* vo    = (const float*)d_in[18];
    float* out = (float*)d_out;

    fp16 *h0, *l0, *h1, *l1;
    cudaGetSymbolAddress((void**)&h0, g_h0);
    cudaGetSymbolAddress((void**)&l0, g_l0);
    cudaGetSymbolAddress((void**)&h1, g_h1);
    cudaGetSymbolAddress((void**)&l1, g_l1);

    cudaFuncSetAttribute(hidden_mma, cudaFuncAttributeMaxDynamicSharedMemorySize, SMEM_TOT);

    prep_kernel<<<(9 * 2 * NCC * NCC + 255) / 256, 256>>>(
        w_in, b_in, gi, bei, mi, vi,
        w_h, b_h, gh, beh, mh, vh,
        w_out, b_out, go, beo, mo, vo);

    const int NPIX = BATCH * HH * WW;
    in_conv_kernel<<<NPIX / 128, 128>>>(X, h0, l0);

    dim3 hgrid(WW / 128, HH / 2, BATCH);
    for (int lyr = 0; lyr < NHID; lyr++) {
        const fp16* sh = (lyr & 1) ? h1 : h0;
        const fp16* sl = (lyr & 1) ? l1 : l0;
        fp16* dh = (lyr & 1) ? h0 : h1;
        fp16* dl = (lyr & 1) ? l0 : l1;
        hidden_mma<<<hgrid, 512, SMEM_TOT>>>(sh, sl, dh, dl);
    }
    // NHID even -> final activations in (h0, l0)
    out_conv_kernel<<<NPIX / 128, 128>>>(h0, l0, X, out);
}

// round 13
// speedup vs baseline: 2.2765x; 1.0670x over previous
#include <cuda_runtime.h>
#include <cuda_fp16.h>
#include <cstdint>

#define BATCH 4
#define HH 256
#define WW 256
#define NCC 64
#define NHID 18
#define EPSV 1e-5f

typedef __half fp16;

// ---------------- device scratch ----------------
__device__ __align__(16) fp16 g_h0[BATCH * HH * WW * NCC];
__device__ __align__(16) fp16 g_l0[BATCH * HH * WW * NCC];
__device__ __align__(16) fp16 g_h1[BATCH * HH * WW * NCC];
__device__ __align__(16) fp16 g_l1[BATCH * HH * WW * NCC];
__device__ __align__(16) fp16 g_whx[9 * 2 * NCC * NCC];   // [tap][term][ci][co]
__device__ float g_bh[NCC];
__device__ __align__(16) float g_win[3 * 9 * NCC];
__device__ float g_bin[NCC];
__device__ __align__(16) float g_wout[NCC * 9 * 3];
__device__ float g_bout[3];

// ---------------- helpers ----------------
__device__ __forceinline__ float selu_f(float x) {
    const float sc = 1.0507009873554805f;
    const float scal = 1.7580993408473766f;
    return x > 0.f ? sc * x : scal * (expf(x) - 1.f);
}
__device__ __forceinline__ uint32_t smem_u32(const void* p) {
    uint32_t a;
    asm("{ .reg .u64 t; cvta.to.shared.u64 t, %1; cvt.u32.u64 %0, t; }" : "=r"(a) : "l"(p));
    return a;
}
__device__ __forceinline__ void cpa16(uint32_t dst, const void* src, bool pred) {
    int sz = pred ? 16 : 0;
    asm volatile("cp.async.cg.shared.global [%0], [%1], 16, %2;" :: "r"(dst), "l"(src), "r"(sz) : "memory");
}
#define CP_COMMIT() asm volatile("cp.async.commit_group;" ::: "memory")
#define CP_WAIT0()  asm volatile("cp.async.wait_group 0;" ::: "memory")

__device__ __forceinline__ void ldsm_x4(uint32_t (&r)[4], uint32_t addr) {
    asm volatile("ldmatrix.sync.aligned.m8n8.x4.shared.b16 {%0,%1,%2,%3}, [%4];"
                 : "=r"(r[0]), "=r"(r[1]), "=r"(r[2]), "=r"(r[3]) : "r"(addr));
}
__device__ __forceinline__ void ldsm_x4t(uint32_t (&r)[4], uint32_t addr) {
    asm volatile("ldmatrix.sync.aligned.m8n8.x4.trans.shared.b16 {%0,%1,%2,%3}, [%4];"
                 : "=r"(r[0]), "=r"(r[1]), "=r"(r[2]), "=r"(r[3]) : "r"(addr));
}
__device__ __forceinline__ void mma16816(float (&d)[4], const uint32_t (&a)[4], uint32_t b0, uint32_t b1) {
    asm volatile("mma.sync.aligned.m16n8k16.row.col.f32.f16.f16.f32 "
                 "{%0,%1,%2,%3}, {%4,%5,%6,%7}, {%8,%9}, {%0,%1,%2,%3};"
                 : "+f"(d[0]), "+f"(d[1]), "+f"(d[2]), "+f"(d[3])
                 : "r"(a[0]), "r"(a[1]), "r"(a[2]), "r"(a[3]), "r"(b0), "r"(b1));
}

// smem layout: bias | A tiles [term(2)][inrow(4)] x 66px x 64ci | W double-buffer
static constexpr int A_TILE = 66 * 128;                   // 8448 bytes per tile
static constexpr int SMEM_A = 1024;
static constexpr int SMEM_WB = SMEM_A + 8 * A_TILE;       // 1024 + 67584 = 68608
static constexpr int WSTAGE = 2 * NCC * NCC * 2;          // 16384 bytes per tap
static constexpr int SMEM_TOT = SMEM_WB + 2 * WSTAGE;     // 101376 (<113.5KB -> 2 CTA/SM)

// ---------------- prep: fold BN, split weights to fp16 hi/lo ----------------
__global__ void prep_kernel(
    const float* __restrict__ w_in, const float* __restrict__ b_in,
    const float* __restrict__ g_in, const float* __restrict__ be_in,
    const float* __restrict__ m_in, const float* __restrict__ v_in,
    const float* __restrict__ w_h,  const float* __restrict__ b_h,
    const float* __restrict__ g_h,  const float* __restrict__ be_h,
    const float* __restrict__ m_h,  const float* __restrict__ v_h,
    const float* __restrict__ w_out, const float* __restrict__ b_out,
    const float* __restrict__ g_out, const float* __restrict__ be_out,
    const float* __restrict__ m_out, const float* __restrict__ v_out)
{
    int idx = blockIdx.x * blockDim.x + threadIdx.x;
    if (idx < 9 * 2 * NCC * NCC) {        // [tap][term][ci][co]
        int co = idx & 63;
        int ci = (idx >> 6) & 63;
        int term = (idx >> 12) & 1;
        int tap = idx >> 13;
        float s = g_h[co] * rsqrtf(v_h[co] + EPSV);
        float wf = w_h[(co * NCC + ci) * 9 + tap] * s;
        fp16 hi = __float2half_rn(wf);
        g_whx[idx] = (term == 0) ? hi : __float2half_rn(wf - __half2float(hi));
    }
    if (idx < 3 * 9 * NCC) {
        int co = idx & 63;
        int rest = idx >> 6;
        int tap = rest % 9;
        int ci = rest / 9;
        float s = g_in[co] * rsqrtf(v_in[co] + EPSV);
        g_win[idx] = w_in[(co * 3 + ci) * 9 + tap] * s;
    }
    if (idx < NCC * 9 * 3) {
        int co = idx % 3;
        int rest = idx / 3;
        int tap = rest % 9;
        int ci = rest / 9;
        float s = g_out[co] * rsqrtf(v_out[co] + EPSV);
        g_wout[idx] = w_out[(co * NCC + ci) * 9 + tap] * s;
    }
    if (idx < NCC) {
        g_bh[idx]  = (b_h[idx]  - m_h[idx])  * (g_h[idx]  * rsqrtf(v_h[idx]  + EPSV)) + be_h[idx];
        g_bin[idx] = (b_in[idx] - m_in[idx]) * (g_in[idx] * rsqrtf(v_in[idx] + EPSV)) + be_in[idx];
    }
    if (idx < 3) {
        g_bout[idx] = (b_out[idx] - m_out[idx]) * (g_out[idx] * rsqrtf(v_out[idx] + EPSV)) + be_out[idx];
    }
}

// ---------------- input conv 3->64 + BN + SELU, NCHW -> NHWC fp16 hi/lo ----------------
__global__ __launch_bounds__(128) void in_conv_kernel(const float* __restrict__ X,
                                                      fp16* __restrict__ oh, fp16* __restrict__ ol)
{
    __shared__ __align__(16) float s_w[3 * 9 * NCC];
    __shared__ __align__(16) float s_b[NCC];
    int tid = threadIdx.x;
    for (int i = tid; i < 3 * 9 * NCC; i += 128) s_w[i] = g_win[i];
    if (tid < NCC) s_b[tid] = g_bin[tid];
    __syncthreads();

    int p = blockIdx.x * 128 + tid;
    int b = p >> 16;
    int y = (p >> 8) & 255;
    int x = p & 255;
    const float* Xb = X + (size_t)b * 3 * HH * WW;

    float4 acc[16];
    #pragma unroll
    for (int q = 0; q < 16; q++) acc[q] = ((const float4*)s_b)[q];

    #pragma unroll
    for (int ci = 0; ci < 3; ci++) {
        #pragma unroll
        for (int dy = 0; dy < 3; dy++) {
            int gy = y + dy - 1;
            #pragma unroll
            for (int dx = 0; dx < 3; dx++) {
                int gx = x + dx - 1;
                float v = 0.f;
                if (gy >= 0 && gy < HH && gx >= 0 && gx < WW)
                    v = Xb[ci * HH * WW + gy * WW + gx];
                const float4* w4 = (const float4*)(s_w + (ci * 9 + dy * 3 + dx) * NCC);
                #pragma unroll
                for (int q = 0; q < 16; q++) {
                    float4 w = w4[q];
                    acc[q].x += v * w.x; acc[q].y += v * w.y;
                    acc[q].z += v * w.z; acc[q].w += v * w.w;
                }
            }
        }
    }
    fp16 hv[64], lv[64];
    #pragma unroll
    for (int q = 0; q < 16; q++) {
        float vv[4] = { acc[q].x, acc[q].y, acc[q].z, acc[q].w };
        #pragma unroll
        for (int j = 0; j < 4; j++) {
            float v = selu_f(vv[j]);
            fp16 h = __float2half_rn(v);
            hv[q * 4 + j] = h;
            lv[q * 4 + j] = __float2half_rn(v - __half2float(h));
        }
    }
    #pragma unroll
    for (int t = 0; t < 8; t++) {
        *(uint4*)(oh + (size_t)p * NCC + t * 8) = *(uint4*)(hv + t * 8);
        *(uint4*)(ol + (size_t)p * NCC + t * 8) = *(uint4*)(lv + t * 8);
    }
}

// ---------------- hidden conv 64->64 via mma.sync HMMA (3-term fp16 split) ----------------
// CTA: 256 thr = 8 warps, 2 CTAs/SM; 2 output rows x 64 px strip; 64 co.
// Warp = (r: row) x (st: 32-px strip) x (nh: co half); per-warp tile M=32, N=32.
// smem A: [term(2)][inrow(4)] x 66 px x 64 ci fp16, 16B-group swizzle.
// W streamed per tap: [term][ci][co] fp16, double buffered; x4.trans loads 2 co-cols.
__global__ __launch_bounds__(256, 2) void hidden_mma(const fp16* __restrict__ ah, const fp16* __restrict__ al,
                                                     fp16* __restrict__ oh, fp16* __restrict__ ol)
{
    extern __shared__ char smem[];
    float* s_bias = (float*)smem;
    uint32_t sAu = smem_u32(smem + SMEM_A);
    uint32_t sWu = smem_u32(smem + SMEM_WB);
    int tid = threadIdx.x;
    int x0 = blockIdx.x * 64;
    int y0 = blockIdx.y * 2;
    int b  = blockIdx.z;

    if (tid < 64) s_bias[tid] = g_bh[tid];

    // --- A halo tile loads: 8 tiles (term x 4 input rows) x 66 px x 8 groups of 16B ---
    for (int j = tid; j < 8 * 66 * 8; j += 256) {
        int g = j & 7;
        int p = (j >> 3) % 66;
        int t3 = (j >> 3) / 66;             // term*4 + ri
        int ri = t3 & 3;
        int gx = x0 - 1 + p, gy = y0 - 1 + ri;
        bool v = (gx >= 0 && gx < WW && gy >= 0 && gy < HH);
        int gxc = v ? gx : 0;
        int gyc = (gy >= 0 && gy < HH) ? gy : 0;
        const fp16* base = (t3 >= 4) ? al : ah;
        const fp16* src = base + ((size_t)((b * HH + gyc) * WW) + gxc) * NCC + g * 8;
        uint32_t dst = sAu + t3 * A_TILE + p * 128 + ((g ^ (p & 7)) << 4);
        cpa16(dst, src, v);
    }
    // --- stage W tap 0 into buf 0 ---
    {
        const char* src = (const char*)g_whx;
        for (int j = tid; j < 1024; j += 256) {
            int g = j & 7, ci = (j >> 3) & 63, term = j >> 9;
            uint32_t dst = sWu + term * 8192 + ci * 128 + ((g ^ (ci & 7)) << 4);
            cpa16(dst, src + term * 8192 + ci * 128 + g * 16, true);
        }
    }
    CP_COMMIT();

    float acc[2][4][4];
    #pragma unroll
    for (int mt = 0; mt < 2; mt++)
        #pragma unroll
        for (int n0 = 0; n0 < 4; n0++)
            #pragma unroll
            for (int k = 0; k < 4; k++) acc[mt][n0][k] = 0.f;

    int lane = tid & 31;
    int w = tid >> 5;
    int r = w >> 2;                 // output row within CTA (0/1)
    int mp = ((w >> 1) & 1) * 32;   // warp's 32-px base
    int nh = w & 1;                 // co half (0/1)
    int mat = lane >> 3, rr = lane & 7;
    int mrow = ((mat & 1) << 3) + rr;   // A m_local within m16 tile
    int kh = mat >> 1;                  // A k-half
    int l16 = lane & 15;                // W ci row within k16
    int csel = lane >> 4;               // W co-column select (x4.trans)

    int wbuf = 0;
    for (int tap = 0; tap < 9; ++tap) {
        CP_WAIT0();
        __syncthreads();
        if (tap < 8) {
            const char* src = (const char*)g_whx + (tap + 1) * WSTAGE;
            uint32_t dstb = sWu + (wbuf ^ 1) * WSTAGE;
            for (int j = tid; j < 1024; j += 256) {
                int g = j & 7, ci = (j >> 3) & 63, term = j >> 9;
                uint32_t dst = dstb + term * 8192 + ci * 128 + ((g ^ (ci & 7)) << 4);
                cpa16(dst, src + term * 8192 + ci * 128 + g * 16, true);
            }
            CP_COMMIT();
        }
        int dy = tap / 3, dx = tap % 3;
        int trow = r + dy;                  // input-row tile index 0..3

        #pragma unroll
        for (int kc = 0; kc < 4; ++kc) {
            uint32_t a_hi[2][4], a_lo[2][4];
            #pragma unroll
            for (int mt = 0; mt < 2; mt++) {
                int s = mp + mt * 16 + mrow + dx;    // strip px 0..65
                int g = kc * 2 + kh;
                uint32_t arow = (uint32_t)(trow * A_TILE + s * 128 + ((g ^ (s & 7)) << 4));
                ldsm_x4(a_hi[mt], sAu + arow);
                ldsm_x4(a_lo[mt], sAu + 4 * A_TILE + arow);
            }
            int ci = kc * 16 + l16;
            uint32_t wrow = sWu + wbuf * WSTAGE + ci * 128;
            uint32_t sw = (ci & 7) << 4;
            #pragma unroll
            for (int p2 = 0; p2 < 2; ++p2) {
                int n0g = nh * 4 + p2 * 2 + csel;    // this lane-group's co column
                uint32_t bh4[4], bl4[4];
                uint32_t waddr = wrow + ((n0g << 4) ^ sw);
                ldsm_x4t(bh4, waddr);
                ldsm_x4t(bl4, waddr + 8192);
                int c0 = p2 * 2;
                mma16816(acc[0][c0],     a_hi[0], bh4[0], bh4[1]);
                mma16816(acc[1][c0],     a_hi[1], bh4[0], bh4[1]);
                mma16816(acc[0][c0 + 1], a_hi[0], bh4[2], bh4[3]);
                mma16816(acc[1][c0 + 1], a_hi[1], bh4[2], bh4[3]);
                mma16816(acc[0][c0],     a_lo[0], bh4[0], bh4[1]);
                mma16816(acc[1][c0],     a_lo[1], bh4[0], bh4[1]);
                mma16816(acc[0][c0 + 1], a_lo[0], bh4[2], bh4[3]);
                mma16816(acc[1][c0 + 1], a_lo[1], bh4[2], bh4[3]);
                mma16816(acc[0][c0],     a_hi[0], bl4[0], bl4[1]);
                mma16816(acc[1][c0],     a_hi[1], bl4[0], bl4[1]);
                mma16816(acc[0][c0 + 1], a_hi[0], bl4[2], bl4[3]);
                mma16816(acc[1][c0 + 1], a_hi[1], bl4[2], bl4[3]);
            }
        }
        __syncthreads();
        wbuf ^= 1;
    }

    // --- epilogue: bias + SELU + fp16 hi/lo split, store NHWC ---
    int q = lane >> 2;
    int cp2 = (lane & 3) << 1;
    int gy = y0 + r;
    #pragma unroll
    for (int mt = 0; mt < 2; ++mt) {
        #pragma unroll
        for (int n0 = 0; n0 < 4; ++n0) {
            int cb = nh * 32 + n0 * 8 + cp2;
            float b0 = s_bias[cb];
            float b1 = s_bias[cb + 1];
            #pragma unroll
            for (int hr = 0; hr < 2; ++hr) {
                int px = mp + mt * 16 + q + hr * 8;
                float v0 = acc[mt][n0][hr * 2 + 0] + b0;
                float v1 = acc[mt][n0][hr * 2 + 1] + b1;
                v0 = selu_f(v0);
                v1 = selu_f(v1);
                fp16 h0 = __float2half_rn(v0);
                fp16 h1 = __float2half_rn(v1);
                fp16 lo0 = __float2half_rn(v0 - __half2float(h0));
                fp16 lo1 = __float2half_rn(v1 - __half2float(h1));
                size_t off = ((size_t)((b * HH + gy) * WW) + (x0 + px)) * NCC + cb;
                *(__half2*)(oh + off) = __halves2half2(h0, h1);
                *(__half2*)(ol + off) = __halves2half2(lo0, lo1);
            }
        }
    }
}

// ---------------- output conv 64->3 + BN + SELU + bayer residual ----------------
__global__ __launch_bounds__(128) void out_conv_kernel(const fp16* __restrict__ ah,
                                                       const fp16* __restrict__ al,
                                                       const float* __restrict__ X,
                                                       float* __restrict__ out)
{
    __shared__ float s_w[NCC * 9 * 3];
    __shared__ float s_b[4];
    int tid = threadIdx.x;
    for (int i = tid; i < NCC * 9 * 3; i += 128) s_w[i] = g_wout[i];
    if (tid < 3) s_b[tid] = g_bout[tid];
    __syncthreads();

    int p = blockIdx.x * 128 + tid;
    int b = p >> 16;
    int y = (p >> 8) & 255;
    int x = p & 255;

    float acc0 = s_b[0], acc1 = s_b[1], acc2 = s_b[2];
    #pragma unroll
    for (int dy = 0; dy < 3; dy++) {
        int gy = y + dy - 1;
        #pragma unroll
        for (int dx = 0; dx < 3; dx++) {
            int gx = x + dx - 1;
            if (gy < 0 || gy >= HH || gx < 0 || gx >= WW) continue;
            int tap = dy * 3 + dx;
            size_t base = ((size_t)b * HH * WW + (size_t)gy * WW + gx) * NCC;
            #pragma unroll
            for (int t = 0; t < 8; t++) {
                uint4 hraw = *(const uint4*)(ah + base + t * 8);
                uint4 lraw = *(const uint4*)(al + base + t * 8);
                const fp16* hp = (const fp16*)&hraw;
                const fp16* lp = (const fp16*)&lraw;
                #pragma unroll
                for (int j = 0; j < 8; j++) {
                    int ci = t * 8 + j;
                    float v = __half2float(hp[j]) + __half2float(lp[j]);
                    const float* w = s_w + (ci * 9 + tap) * 3;
                    acc0 += v * w[0]; acc1 += v * w[1]; acc2 += v * w[2];
                }
            }
        }
    }
    float sel[3] = { selu_f(acc0), selu_f(acc1), selu_f(acc2) };

    #pragma unroll
    for (int c = 0; c < 3; c++) {
        const float* Xc = X + ((size_t)b * 3 + c) * HH * WW;
        float xv = Xc[y * WW + x];
        float l = (x > 0)       ? Xc[y * WW + x - 1] : 0.f;
        float rr = (x < WW - 1) ? Xc[y * WW + x + 1] : 0.f;
        float t = (y > 0)       ? Xc[(y - 1) * WW + x] : 0.f;
        float bt = (y < HH - 1) ? Xc[(y + 1) * WW + x] : 0.f;
        float nb_sum = l + rr + t + bt;
        float nb_cnt = (l > 0.f) + (rr > 0.f) + (t > 0.f) + (bt > 0.f);
        float mean = nb_cnt > 0.f ? nb_sum / nb_cnt : 0.f;
        float res = (xv == 0.f) ? mean : xv;
        out[((size_t)b * 3 + c) * HH * WW + (size_t)y * WW + x] = sel[c] + res;
    }
}

// ---------------- launch ----------------
extern "C" void kernel_launch(void* const* d_in, const int* in_sizes, int n_in,
                              void* d_out, int out_size)
{
    const float* X     = (const float*)d_in[0];
    const float* w_in  = (const float*)d_in[1];
    const float* b_in  = (const float*)d_in[2];
    const float* gi    = (const float*)d_in[3];
    const float* bei   = (const float*)d_in[4];
    const float* mi    = (const float*)d_in[5];
    const float* vi    = (const float*)d_in[6];
    const float* w_h   = (const float*)d_in[7];
    const float* b_h   = (const float*)d_in[8];
    const float* gh    = (const float*)d_in[9];
    const float* beh   = (const float*)d_in[10];
    const float* mh    = (const float*)d_in[11];
    const float* vh    = (const float*)d_in[12];
    const float* w_out = (const float*)d_in[13];
    const float* b_out = (const float*)d_in[14];
    const float* go    = (const float*)d_in[15];
    const float* beo   = (const float*)d_in[16];
    const float* mo    = (const float*)d_in[17];
    const float* vo    = (const float*)d_in[18];
    float* out = (float*)d_out;

    fp16 *h0, *l0, *h1, *l1;
    cudaGetSymbolAddress((void**)&h0, g_h0);
    cudaGetSymbolAddress((void**)&l0, g_l0);
    cudaGetSymbolAddress((void**)&h1, g_h1);
    cudaGetSymbolAddress((void**)&l1, g_l1);

    cudaFuncSetAttribute(hidden_mma, cudaFuncAttributeMaxDynamicSharedMemorySize, SMEM_TOT);

    prep_kernel<<<(9 * 2 * NCC * NCC + 255) / 256, 256>>>(
        w_in, b_in, gi, bei, mi, vi,
        w_h, b_h, gh, beh, mh, vh,
        w_out, b_out, go, beo, mo, vo);

    const int NPIX = BATCH * HH * WW;
    in_conv_kernel<<<NPIX / 128, 128>>>(X, h0, l0);

    dim3 hgrid(WW / 64, HH / 2, BATCH);
    for (int lyr = 0; lyr < NHID; lyr++) {
        const fp16* sh = (lyr & 1) ? h1 : h0;
        const fp16* sl = (lyr & 1) ? l1 : l0;
        fp16* dh = (lyr & 1) ? h0 : h1;
        fp16* dl = (lyr & 1) ? l0 : l1;
        hidden_mma<<<hgrid, 256, SMEM_TOT>>>(sh, sl, dh, dl);
    }
    // NHID even -> final activations in (h0, l0)
    out_conv_kernel<<<NPIX / 128, 128>>>(h0, l0, X, out);
}